// round 11
// baseline (speedup 1.0000x reference)
#include <cuda_runtime.h>
#include <cuda_bf16.h>
#include <cuda_fp16.h>
#include <stdint.h>

#define N_NODES 50000
#define E_EDGES 800000
#define INC 128
#define HID 256
#define OUTC 51
#define NB_SCAN 196   // ceil(50000/256)

// ---------------------------------------------------------------------------
// Scratch (static device globals -- allocation-free per harness rules)
// ---------------------------------------------------------------------------
__device__ __align__(16) __nv_bfloat16 g_x0h[N_NODES * INC], g_x0l[N_NODES * INC];
__device__ __align__(16) __half        g_x0p[N_NODES * INC];          // fp16 x0 (messages)
__device__ __align__(16) __nv_bfloat16 g_a1h[N_NODES * INC], g_a1l[N_NODES * INC];
__device__ __align__(16) __half        g_x1p[N_NODES * HID];          // fp16 x1 (messages)
__device__ __align__(16) __nv_bfloat16 g_x1h[N_NODES * HID], g_x1l[N_NODES * HID];
__device__ __align__(16) __nv_bfloat16 g_a2h[N_NODES * HID], g_a2l[N_NODES * HID];
__device__ __align__(16) __nv_bfloat16 g_x2h[N_NODES * HID], g_x2l[N_NODES * HID];
__device__ __align__(16) __nv_bfloat16 g_wr1h[HID * INC],  g_wr1l[HID * INC];
__device__ __align__(16) __nv_bfloat16 g_wo1h[HID * INC],  g_wo1l[HID * INC];
__device__ __align__(16) __nv_bfloat16 g_wr2h[HID * HID],  g_wr2l[HID * HID];
__device__ __align__(16) __nv_bfloat16 g_wo2h[HID * HID],  g_wo2l[HID * HID];
__device__ __align__(16) __nv_bfloat16 g_linh[OUTC * 2 * HID], g_linl[OUTC * 2 * HID];
// CSR (payload packed: x = src, y = weight bits)
__device__ int   g_deg[N_NODES];
__device__ int   g_off[N_NODES];
__device__ int   g_cur[N_NODES];
__device__ uint2 g_edge[E_EDGES];
__device__ int   g_total;
__device__ int   g_idx_is64;

// ---------------------------------------------------------------------------
// PTX helpers (baseline PTX only)
// ---------------------------------------------------------------------------
__device__ __forceinline__ uint32_t smem_u32(const void* p) {
    uint32_t a;
    asm("{ .reg .u64 t; cvta.to.shared.u64 t, %1; cvt.u32.u64 %0, t; }" : "=r"(a) : "l"(p));
    return a;
}
__device__ __forceinline__ void ldsm4(uint32_t addr, uint32_t& r0, uint32_t& r1,
                                      uint32_t& r2, uint32_t& r3) {
    asm volatile("ldmatrix.sync.aligned.m8n8.x4.shared.b16 {%0,%1,%2,%3}, [%4];"
                 : "=r"(r0), "=r"(r1), "=r"(r2), "=r"(r3) : "r"(addr));
}
__device__ __forceinline__ void mma16816(float* c, const uint32_t* a, const uint32_t* b) {
    asm volatile("mma.sync.aligned.m16n8k16.row.col.f32.bf16.bf16.f32 "
                 "{%0,%1,%2,%3}, {%4,%5,%6,%7}, {%8,%9}, {%0,%1,%2,%3};"
                 : "+f"(c[0]), "+f"(c[1]), "+f"(c[2]), "+f"(c[3])
                 : "r"(a[0]), "r"(a[1]), "r"(a[2]), "r"(a[3]), "r"(b[0]), "r"(b[1]));
}
__device__ __forceinline__ uint32_t tile_addr(uint32_t base, int r, int u) {
    int up = u ^ ((r >> 1) & 3);
    return base + (uint32_t)(r * 4 + up) * 16u;
}
__device__ __forceinline__ void cp16(uint32_t daddr, const void* src, int sz) {
    asm volatile("cp.async.cg.shared.global [%0], [%1], 16, %2;"
                 :: "r"(daddr), "l"(src), "r"(sz) : "memory");
}

// ---------------------------------------------------------------------------
// dtype detect + zero scan base + zero deg (grid covers N_NODES)
// ---------------------------------------------------------------------------
__global__ void detect_and_zero(const void* __restrict__ ei) {
    int i = blockIdx.x * blockDim.x + threadIdx.x;
    if (i < N_NODES) g_deg[i] = 0;
    if (blockIdx.x == 0 && threadIdx.x < 32) {
        int t = threadIdx.x;
        const long long* p = (const long long*)ei;
        int bad = 0;
        for (int k = t; k < 256; k += 32) {
            long long v = p[k];
            if (v < 0 || v >= N_NODES) bad = 1;
        }
        unsigned m = __ballot_sync(0xffffffffu, bad);
        if (t == 0) { g_idx_is64 = (m == 0u); g_total = 0; }
    }
}
__device__ __forceinline__ void load_edge(const void* ei, int e, int& src, int& dst) {
    if (g_idx_is64) {
        src = (int)((const long long*)ei)[e];
        dst = (int)((const long long*)ei)[E_EDGES + e];
    } else {
        src = ((const int*)ei)[e];
        dst = ((const int*)ei)[E_EDGES + e];
    }
}

// ---------------------------------------------------------------------------
// CSR build: hist -> one-pass scan (atomic base) -> bucket (packed payload)
// ---------------------------------------------------------------------------
__global__ void hist_dst(const void* __restrict__ ei) {
    int e = blockIdx.x * blockDim.x + threadIdx.x;
    if (e >= E_EDGES) return;
    int src, dst;
    load_edge(ei, e, src, dst);
    atomicAdd(&g_deg[dst], 1);
}
__global__ void scan_one() {
    __shared__ int s[256];
    __shared__ int sh_base;
    int b = blockIdx.x, t = threadIdx.x, i = b * 256 + t;
    int v = (i < N_NODES) ? g_deg[i] : 0;
    s[t] = v;
    __syncthreads();
    for (int o = 1; o < 256; o <<= 1) {
        int u = (t >= o) ? s[t - o] : 0;
        __syncthreads();
        s[t] += u;
        __syncthreads();
    }
    if (t == 255) sh_base = atomicAdd(&g_total, s[255]);
    __syncthreads();
    if (i < N_NODES) {
        int off = sh_base + s[t] - v;
        g_off[i] = off;
        g_cur[i] = off;
    }
}
__global__ void bucket_edges(const void* __restrict__ ei, const float* __restrict__ ew) {
    int e = blockIdx.x * blockDim.x + threadIdx.x;
    if (e >= E_EDGES) return;
    int src, dst;
    load_edge(ei, e, src, dst);
    int pos = atomicAdd(&g_cur[dst], 1);
    g_edge[pos] = make_uint2((unsigned)src, __float_as_uint(ew[e]));
}

// ---------------------------------------------------------------------------
// bf16 hi/lo split helpers
// ---------------------------------------------------------------------------
__device__ __forceinline__ void split1(float v, __nv_bfloat16& h, __nv_bfloat16& l) {
    h = __float2bfloat16(v);
    l = __float2bfloat16(v - __bfloat162float(h));
}
__device__ __forceinline__ void store_split4(float4 a, __nv_bfloat16* ph, __nv_bfloat16* pl) {
    __nv_bfloat16 h0, h1, h2, h3, l0, l1, l2, l3;
    split1(a.x, h0, l0); split1(a.y, h1, l1); split1(a.z, h2, l2); split1(a.w, h3, l3);
    ((__nv_bfloat162*)ph)[0] = __halves2bfloat162(h0, h1);
    ((__nv_bfloat162*)ph)[1] = __halves2bfloat162(h2, h3);
    ((__nv_bfloat162*)pl)[0] = __halves2bfloat162(l0, l1);
    ((__nv_bfloat162*)pl)[1] = __halves2bfloat162(l2, l3);
}

// ---------------------------------------------------------------------------
// Fused prep: x0 split + fp16 copy + 5 weight transpose-splits
// ---------------------------------------------------------------------------
#define PX0   (N_NODES * INC)
#define PW1   (INC * HID)
#define PW2   (HID * HID)
#define PLIN  (2 * HID * OUTC)
#define PWSUM (2 * PW1 + 2 * PW2 + PLIN)
#define PREP_TOTAL (PX0 + PWSUM)

__global__ void prep_all(const float* __restrict__ x0,
                         const float* __restrict__ wr1, const float* __restrict__ wo1,
                         const float* __restrict__ wr2, const float* __restrict__ wo2,
                         const float* __restrict__ lin) {
    long long i = (long long)blockIdx.x * blockDim.x + threadIdx.x;
    if (i >= PREP_TOTAL) return;
    __nv_bfloat16 hh, ll;
    if (i < PX0) {
        float v = x0[i];
        split1(v, hh, ll);
        g_x0h[i] = hh; g_x0l[i] = ll;
        g_x0p[i] = __float2half(v);
        return;
    }
    long long j = i - PX0;
    const float* W; __nv_bfloat16 *th, *tl; int K, M; long long o;
    if (j < PW1)                { W = wr1; th = g_wr1h; tl = g_wr1l; K = INC; M = HID; o = j; }
    else if (j < 2 * PW1)       { W = wo1; th = g_wo1h; tl = g_wo1l; K = INC; M = HID; o = j - PW1; }
    else if (j < 2 * PW1 + PW2) { W = wr2; th = g_wr2h; tl = g_wr2l; K = HID; M = HID; o = j - 2 * PW1; }
    else if (j < 2 * PW1 + 2 * PW2) { W = wo2; th = g_wo2h; tl = g_wo2l; K = HID; M = HID; o = j - 2 * PW1 - PW2; }
    else                        { W = lin; th = g_linh; tl = g_linl; K = 2 * HID; M = OUTC; o = j - 2 * PW1 - 2 * PW2; }
    int k = (int)(o / M), m = (int)(o % M);
    split1(W[o], hh, ll);
    th[(size_t)m * K + k] = hh;
    tl[(size_t)m * K + k] = ll;
}

// ---------------------------------------------------------------------------
// CSR aggregation (warp per dst, fp16 gather, x2-unrolled, bf16-split output)
// ---------------------------------------------------------------------------
__global__ __launch_bounds__(256)
void agg_csr_128(const __half* __restrict__ x,
                 __nv_bfloat16* __restrict__ oh, __nv_bfloat16* __restrict__ ol) {
    int d = blockIdx.x * 8 + (threadIdx.x >> 5);
    if (d >= N_NODES) return;
    int lane = threadIdx.x & 31;
    int beg = g_off[d], end = g_cur[d];
    float4 a0 = make_float4(0.f, 0.f, 0.f, 0.f);
    float4 a1 = make_float4(0.f, 0.f, 0.f, 0.f);
    int k = beg;
    for (; k + 1 < end; k += 2) {
        uint2 e0 = g_edge[k], e1 = g_edge[k + 1];
        float w0 = __uint_as_float(e0.y), w1 = __uint_as_float(e1.y);
        uint2 p0 = ((const uint2*)(x + (size_t)e0.x * INC))[lane];
        uint2 p1 = ((const uint2*)(x + (size_t)e1.x * INC))[lane];
        float2 f00 = __half22float2(*(const __half2*)&p0.x);
        float2 f01 = __half22float2(*(const __half2*)&p0.y);
        float2 f10 = __half22float2(*(const __half2*)&p1.x);
        float2 f11 = __half22float2(*(const __half2*)&p1.y);
        a0.x = fmaf(w0, f00.x, a0.x); a0.y = fmaf(w0, f00.y, a0.y);
        a0.z = fmaf(w0, f01.x, a0.z); a0.w = fmaf(w0, f01.y, a0.w);
        a1.x = fmaf(w1, f10.x, a1.x); a1.y = fmaf(w1, f10.y, a1.y);
        a1.z = fmaf(w1, f11.x, a1.z); a1.w = fmaf(w1, f11.y, a1.w);
    }
    if (k < end) {
        uint2 e0 = g_edge[k];
        float w0 = __uint_as_float(e0.y);
        uint2 p0 = ((const uint2*)(x + (size_t)e0.x * INC))[lane];
        float2 f00 = __half22float2(*(const __half2*)&p0.x);
        float2 f01 = __half22float2(*(const __half2*)&p0.y);
        a0.x = fmaf(w0, f00.x, a0.x); a0.y = fmaf(w0, f00.y, a0.y);
        a0.z = fmaf(w0, f01.x, a0.z); a0.w = fmaf(w0, f01.y, a0.w);
    }
    a0.x += a1.x; a0.y += a1.y; a0.z += a1.z; a0.w += a1.w;
    store_split4(a0, oh + (size_t)d * INC + lane * 4, ol + (size_t)d * INC + lane * 4);
}

__global__ __launch_bounds__(256)
void agg_csr_256h(const __half* __restrict__ x,
                  __nv_bfloat16* __restrict__ oh, __nv_bfloat16* __restrict__ ol) {
    int d = blockIdx.x * 8 + (threadIdx.x >> 5);
    if (d >= N_NODES) return;
    int lane = threadIdx.x & 31;
    int beg = g_off[d], end = g_cur[d];
    float acc0[8], acc1[8];
#pragma unroll
    for (int j = 0; j < 8; ++j) { acc0[j] = 0.f; acc1[j] = 0.f; }
    int k = beg;
    for (; k + 1 < end; k += 2) {
        uint2 e0 = g_edge[k], e1 = g_edge[k + 1];
        float w0 = __uint_as_float(e0.y), w1 = __uint_as_float(e1.y);
        uint4 p0 = ((const uint4*)(x + (size_t)e0.x * HID))[lane];
        uint4 p1 = ((const uint4*)(x + (size_t)e1.x * HID))[lane];
        const __half2* h0 = (const __half2*)&p0;
        const __half2* h1 = (const __half2*)&p1;
#pragma unroll
        for (int j = 0; j < 4; ++j) {
            float2 f0 = __half22float2(h0[j]);
            float2 f1 = __half22float2(h1[j]);
            acc0[2 * j]     = fmaf(w0, f0.x, acc0[2 * j]);
            acc0[2 * j + 1] = fmaf(w0, f0.y, acc0[2 * j + 1]);
            acc1[2 * j]     = fmaf(w1, f1.x, acc1[2 * j]);
            acc1[2 * j + 1] = fmaf(w1, f1.y, acc1[2 * j + 1]);
        }
    }
    if (k < end) {
        uint2 e0 = g_edge[k];
        float w0 = __uint_as_float(e0.y);
        uint4 p0 = ((const uint4*)(x + (size_t)e0.x * HID))[lane];
        const __half2* h0 = (const __half2*)&p0;
#pragma unroll
        for (int j = 0; j < 4; ++j) {
            float2 f0 = __half22float2(h0[j]);
            acc0[2 * j]     = fmaf(w0, f0.x, acc0[2 * j]);
            acc0[2 * j + 1] = fmaf(w0, f0.y, acc0[2 * j + 1]);
        }
    }
#pragma unroll
    for (int j = 0; j < 8; ++j) acc0[j] += acc1[j];
    float4 a0 = make_float4(acc0[0], acc0[1], acc0[2], acc0[3]);
    float4 a1 = make_float4(acc0[4], acc0[5], acc0[6], acc0[7]);
    size_t o = (size_t)d * HID + lane * 8;
    store_split4(a0, oh + o,     ol + o);
    store_split4(a1, oh + o + 4, ol + o + 4);
}

// ---------------------------------------------------------------------------
// Pipelined bf16 split-precision dual-source GEMM (cp.async, 2 stages)
// ---------------------------------------------------------------------------
template <int BN>
__global__ __launch_bounds__(256)
void gemm_mma(const __nv_bfloat16* __restrict__ A1h, const __nv_bfloat16* __restrict__ A1l, int K1,
              const __nv_bfloat16* __restrict__ A2h, const __nv_bfloat16* __restrict__ A2l, int K2,
              const __nv_bfloat16* __restrict__ B1h, const __nv_bfloat16* __restrict__ B1l, int pb1,
              const __nv_bfloat16* __restrict__ B2h, const __nv_bfloat16* __restrict__ B2l, int pb2,
              const float* __restrict__ bias,
              float* __restrict__ outF, __half* __restrict__ outP,
              __nv_bfloat16* __restrict__ outH, __nv_bfloat16* __restrict__ outL,
              int Mout, int doRelu) {
    constexpr int NG = BN / 16;
    constexpr int NQ = BN / 32;
    constexpr int A_ELE = 128 * 32;
    constexpr int B_ELE = BN * 32;
    constexpr int STG = 2 * A_ELE + 2 * B_ELE;

    extern __shared__ __align__(16) __nv_bfloat16 sm[];
    uint32_t base0 = smem_u32(sm);

    int tid = threadIdx.x, wid = tid >> 5, lane = tid & 31;
    int wm = (wid & 3) * 32;
    int wn = (wid >> 2) * (BN / 2);
    int row0 = blockIdx.x * 128;
    int col0 = blockIdx.y * BN;
    int rowsA = N_NODES - row0; if (rowsA > 128) rowsA = 128;
    int rowsB = Mout - col0;    if (rowsB > BN) rowsB = BN;

    const int nc1 = K1 / 32;
    const int NC = nc1 + K2 / 32;

    auto stage_chunk = [&](int c) {
        const __nv_bfloat16 *Ah, *Al, *Bh, *Bl;
        int pa, pb, kcol;
        if (c < nc1) { Ah = A1h; Al = A1l; pa = K1; Bh = B1h; Bl = B1l; pb = pb1; kcol = c * 32; }
        else         { Ah = A2h; Al = A2l; pa = K2; Bh = B2h; Bl = B2l; pb = pb2; kcol = (c - nc1) * 32; }
        Ah += (size_t)row0 * pa; Al += (size_t)row0 * pa;
        Bh += (size_t)col0 * pb; Bl += (size_t)col0 * pb;
        uint32_t sb = base0 + (uint32_t)(c & 1) * STG * 2;
        for (int U = tid; U < 512; U += 256) {
            int r = U >> 2, u = U & 3;
            int up = u ^ ((r >> 1) & 3);
            int rs = (r < rowsA) ? r : 0;
            int sz = (r < rowsA) ? 16 : 0;
            uint32_t da = sb + (uint32_t)(r * 4 + up) * 16u;
            cp16(da,             Ah + (size_t)rs * pa + kcol + u * 8, sz);
            cp16(da + A_ELE * 2, Al + (size_t)rs * pa + kcol + u * 8, sz);
        }
        uint32_t bb = sb + 2u * (2 * A_ELE);
        for (int U = tid; U < BN * 4; U += 256) {
            int r = U >> 2, u = U & 3;
            int up = u ^ ((r >> 1) & 3);
            int rs = (r < rowsB) ? r : 0;
            int sz = (r < rowsB) ? 16 : 0;
            uint32_t da = bb + (uint32_t)(r * 4 + up) * 16u;
            cp16(da,             Bh + (size_t)rs * pb + kcol + u * 8, sz);
            cp16(da + B_ELE * 2, Bl + (size_t)rs * pb + kcol + u * 8, sz);
        }
    };

    float acc[2][NG][4];
#pragma unroll
    for (int i = 0; i < 2; ++i)
#pragma unroll
        for (int j = 0; j < NG; ++j)
#pragma unroll
            for (int q = 0; q < 4; ++q) acc[i][j][q] = 0.f;

    stage_chunk(0);
    asm volatile("cp.async.commit_group;" ::: "memory");

    for (int c = 0; c < NC; ++c) {
        if (c + 1 < NC) {
            stage_chunk(c + 1);
            asm volatile("cp.async.commit_group;" ::: "memory");
            asm volatile("cp.async.wait_group 1;" ::: "memory");
        } else {
            asm volatile("cp.async.wait_group 0;" ::: "memory");
        }
        __syncthreads();

        uint32_t sb = base0 + (uint32_t)(c & 1) * STG * 2;
        uint32_t bAh = sb, bAl = sb + A_ELE * 2;
        uint32_t bBh = sb + 2u * (2 * A_ELE), bBl = bBh + B_ELE * 2;

#pragma unroll
        for (int ks = 0; ks < 2; ++ks) {
            int ksu = ks * 2;
            uint32_t fah[2][4], fal[2][4];
#pragma unroll
            for (int mt = 0; mt < 2; ++mt) {
                int r = wm + mt * 16 + (lane & 15);
                int u = ksu + (lane >> 4);
                ldsm4(tile_addr(bAh, r, u), fah[mt][0], fah[mt][1], fah[mt][2], fah[mt][3]);
                ldsm4(tile_addr(bAl, r, u), fal[mt][0], fal[mt][1], fal[mt][2], fal[mt][3]);
            }
            uint32_t fbh[NQ][4], fbl[NQ][4];
#pragma unroll
            for (int q = 0; q < NQ; ++q) {
                int r = wn + q * 16 + (lane & 7) + ((lane & 16) ? 8 : 0);
                int u = ksu + ((lane >> 3) & 1);
                ldsm4(tile_addr(bBh, r, u), fbh[q][0], fbh[q][1], fbh[q][2], fbh[q][3]);
                ldsm4(tile_addr(bBl, r, u), fbl[q][0], fbl[q][1], fbl[q][2], fbl[q][3]);
            }
#pragma unroll
            for (int mt = 0; mt < 2; ++mt)
#pragma unroll
                for (int ng = 0; ng < NG; ++ng) {
                    const uint32_t* bpH = &fbh[ng >> 1][(ng & 1) * 2];
                    const uint32_t* bpL = &fbl[ng >> 1][(ng & 1) * 2];
                    mma16816(acc[mt][ng], fah[mt], bpH);
                    mma16816(acc[mt][ng], fah[mt], bpL);
                    mma16816(acc[mt][ng], fal[mt], bpH);
                }
        }
        __syncthreads();
    }

    // Epilogue
#pragma unroll
    for (int mt = 0; mt < 2; ++mt) {
        int rg = row0 + wm + mt * 16 + (lane >> 2);
#pragma unroll
        for (int half = 0; half < 2; ++half) {
            int r = rg + half * 8;
            if (r >= N_NODES) continue;
#pragma unroll
            for (int ng = 0; ng < NG; ++ng) {
                int c0 = col0 + wn + ng * 8 + (lane & 3) * 2;
#pragma unroll
                for (int q = 0; q < 2; ++q) {
                    int c = c0 + q;
                    if (c >= Mout) continue;
                    float v = acc[mt][ng][half * 2 + q] + bias[c];
                    if (doRelu) v = fmaxf(v, 0.f);
                    size_t idx = (size_t)r * Mout + c;
                    if (outF) outF[idx] = v;
                    if (outP) outP[idx] = __float2half(v);
                    if (outH) {
                        __nv_bfloat16 hh, ll;
                        split1(v, hh, ll);
                        outH[idx] = hh;
                        outL[idx] = ll;
                    }
                }
            }
        }
    }
}

// ---------------------------------------------------------------------------
extern "C" void kernel_launch(void* const* d_in, const int* in_sizes, int n_in,
                              void* d_out, int out_size) {
    const float* x0      = (const float*)d_in[0];
    const void*  ei      = d_in[1];
    const float* ew      = (const float*)d_in[2];
    const float* w_rel1  = (const float*)d_in[3];
    const float* b1      = (const float*)d_in[4];
    const float* w_root1 = (const float*)d_in[5];
    const float* w_rel2  = (const float*)d_in[6];
    const float* b2      = (const float*)d_in[7];
    const float* w_root2 = (const float*)d_in[8];
    const float* lin_w   = (const float*)d_in[9];
    const float* lin_b   = (const float*)d_in[10];
    float*       out     = (float*)d_out;

#define SYM(p, s) cudaGetSymbolAddress((void**)&p, s)
    __nv_bfloat16 *x0h, *x0l, *a1h, *a1l, *x1h, *x1l, *a2h, *a2l, *x2h, *x2l;
    __nv_bfloat16 *wr1h, *wr1l, *wo1h, *wo1l, *wr2h, *wr2l, *wo2h, *wo2l, *linh, *linl;
    __half *x0p, *x1p;
    SYM(x0h, g_x0h); SYM(x0l, g_x0l); SYM(x0p, g_x0p);
    SYM(a1h, g_a1h); SYM(a1l, g_a1l);
    SYM(x1p, g_x1p); SYM(x1h, g_x1h); SYM(x1l, g_x1l);
    SYM(a2h, g_a2h); SYM(a2l, g_a2l); SYM(x2h, g_x2h); SYM(x2l, g_x2l);
    SYM(wr1h, g_wr1h); SYM(wr1l, g_wr1l); SYM(wo1h, g_wo1h); SYM(wo1l, g_wo1l);
    SYM(wr2h, g_wr2h); SYM(wr2l, g_wr2l); SYM(wo2h, g_wo2h); SYM(wo2l, g_wo2l);
    SYM(linh, g_linh); SYM(linl, g_linl);
#undef SYM

    const int SM128 = 2 * (2 * 128 * 32 + 2 * 128 * 32) * 2;  // 65536 B
    const int SM64  = 2 * (2 * 128 * 32 + 2 * 64 * 32) * 2;   // 49152 B
    cudaFuncSetAttribute(gemm_mma<128>, cudaFuncAttributeMaxDynamicSharedMemorySize, SM128);
    cudaFuncSetAttribute(gemm_mma<64>,  cudaFuncAttributeMaxDynamicSharedMemorySize, SM64);

    const int eblk = (E_EDGES + 255) / 256;
    const int wblk = (N_NODES + 7) / 8;
    const int gblk = (N_NODES + 127) / 128;   // 391

    // 0) detect + deg zero, then fused prep (serial, single stream)
    detect_and_zero<<<NB_SCAN, 256>>>(ei);
    prep_all<<<(PREP_TOTAL + 255) / 256, 256>>>(x0, w_rel1, w_root1, w_rel2, w_root2, lin_w);

    // 1) CSR build
    hist_dst<<<eblk, 256>>>(ei);
    scan_one<<<NB_SCAN, 256>>>();
    bucket_edges<<<eblk, 256>>>(ei, ew);

    // 2) layer 1
    agg_csr_128<<<wblk, 256>>>(x0p, a1h, a1l);
    gemm_mma<128><<<dim3(gblk, 2), 256, SM128>>>(a1h, a1l, INC, x0h, x0l, INC,
                                                 wr1h, wr1l, INC, wo1h, wo1l, INC,
                                                 b1, (float*)0, x1p, x1h, x1l, HID, 1);
    // 3) layer 2
    agg_csr_256h<<<wblk, 256>>>(x1p, a2h, a2l);
    gemm_mma<128><<<dim3(gblk, 2), 256, SM128>>>(a2h, a2l, HID, x1h, x1l, HID,
                                                 wr2h, wr2l, HID, wo2h, wo2l, HID,
                                                 b2, (float*)0, (__half*)0, x2h, x2l, HID, 1);
    // 4) head
    gemm_mma<64><<<dim3(gblk, 1), 256, SM64>>>(x1h, x1l, HID, x2h, x2l, HID,
                                               linh, linl, 2 * HID, linh + HID, linl + HID, 2 * HID,
                                               lin_b, out, (__half*)0,
                                               (__nv_bfloat16*)0, (__nv_bfloat16*)0,
                                               OUTC, 0);
}

// round 12
// speedup vs baseline: 1.0020x; 1.0020x over previous
#include <cuda_runtime.h>
#include <cuda_bf16.h>
#include <cuda_fp16.h>
#include <stdint.h>

#define N_NODES 50000
#define E_EDGES 800000
#define INC 128
#define HID 256
#define OUTC 51
#define NB_SCAN 196   // ceil(50000/256)

// ---------------------------------------------------------------------------
// Scratch (static device globals -- allocation-free per harness rules)
// ---------------------------------------------------------------------------
__device__ __align__(16) __nv_bfloat16 g_x0h[N_NODES * INC], g_x0l[N_NODES * INC];
__device__ __align__(16) __half        g_x0p[N_NODES * INC];          // fp16 x0 (messages)
__device__ __align__(16) __nv_bfloat16 g_a1h[N_NODES * INC], g_a1l[N_NODES * INC];
__device__ __align__(16) __half        g_x1p[N_NODES * HID];          // fp16 x1 (messages)
__device__ __align__(16) __nv_bfloat16 g_x1h[N_NODES * HID], g_x1l[N_NODES * HID];
__device__ __align__(16) __nv_bfloat16 g_a2h[N_NODES * HID], g_a2l[N_NODES * HID];
__device__ __align__(16) __nv_bfloat16 g_x2h[N_NODES * HID], g_x2l[N_NODES * HID];
__device__ __align__(16) __nv_bfloat16 g_wr1h[HID * INC],  g_wr1l[HID * INC];
__device__ __align__(16) __nv_bfloat16 g_wo1h[HID * INC],  g_wo1l[HID * INC];
__device__ __align__(16) __nv_bfloat16 g_wr2h[HID * HID],  g_wr2l[HID * HID];
__device__ __align__(16) __nv_bfloat16 g_wo2h[HID * HID],  g_wo2l[HID * HID];
__device__ __align__(16) __nv_bfloat16 g_linh[OUTC * 2 * HID], g_linl[OUTC * 2 * HID];
// CSR (payload packed: x = src, y = weight bits; 16B-aligned for uint4 pair loads)
__device__ int   g_deg[N_NODES];
__device__ int   g_off[N_NODES];
__device__ int   g_cur[N_NODES];
__device__ __align__(16) uint2 g_edge[E_EDGES + 4];   // +pad for pair-load tail
__device__ int   g_total;
__device__ int   g_idx_is64;

// ---------------------------------------------------------------------------
// PTX helpers (baseline PTX only)
// ---------------------------------------------------------------------------
__device__ __forceinline__ uint32_t smem_u32(const void* p) {
    uint32_t a;
    asm("{ .reg .u64 t; cvta.to.shared.u64 t, %1; cvt.u32.u64 %0, t; }" : "=r"(a) : "l"(p));
    return a;
}
__device__ __forceinline__ void ldsm4(uint32_t addr, uint32_t& r0, uint32_t& r1,
                                      uint32_t& r2, uint32_t& r3) {
    asm volatile("ldmatrix.sync.aligned.m8n8.x4.shared.b16 {%0,%1,%2,%3}, [%4];"
                 : "=r"(r0), "=r"(r1), "=r"(r2), "=r"(r3) : "r"(addr));
}
__device__ __forceinline__ void mma16816(float* c, const uint32_t* a, const uint32_t* b) {
    asm volatile("mma.sync.aligned.m16n8k16.row.col.f32.bf16.bf16.f32 "
                 "{%0,%1,%2,%3}, {%4,%5,%6,%7}, {%8,%9}, {%0,%1,%2,%3};"
                 : "+f"(c[0]), "+f"(c[1]), "+f"(c[2]), "+f"(c[3])
                 : "r"(a[0]), "r"(a[1]), "r"(a[2]), "r"(a[3]), "r"(b[0]), "r"(b[1]));
}
__device__ __forceinline__ uint32_t tile_addr(uint32_t base, int r, int u) {
    int up = u ^ ((r >> 1) & 3);
    return base + (uint32_t)(r * 4 + up) * 16u;
}
__device__ __forceinline__ void cp16(uint32_t daddr, const void* src, int sz) {
    asm volatile("cp.async.cg.shared.global [%0], [%1], 16, %2;"
                 :: "r"(daddr), "l"(src), "r"(sz) : "memory");
}

// ---------------------------------------------------------------------------
// dtype detect + zero scan base + zero deg (grid covers N_NODES)
// ---------------------------------------------------------------------------
__global__ void detect_and_zero(const void* __restrict__ ei) {
    int i = blockIdx.x * blockDim.x + threadIdx.x;
    if (i < N_NODES) g_deg[i] = 0;
    if (blockIdx.x == 0 && threadIdx.x < 32) {
        int t = threadIdx.x;
        const long long* p = (const long long*)ei;
        int bad = 0;
        for (int k = t; k < 256; k += 32) {
            long long v = p[k];
            if (v < 0 || v >= N_NODES) bad = 1;
        }
        unsigned m = __ballot_sync(0xffffffffu, bad);
        if (t == 0) { g_idx_is64 = (m == 0u); g_total = 0; }
    }
}
__device__ __forceinline__ void load_edge(const void* ei, int e, int& src, int& dst) {
    if (g_idx_is64) {
        src = (int)((const long long*)ei)[e];
        dst = (int)((const long long*)ei)[E_EDGES + e];
    } else {
        src = ((const int*)ei)[e];
        dst = ((const int*)ei)[E_EDGES + e];
    }
}

// ---------------------------------------------------------------------------
// CSR build: hist -> one-pass scan (atomic base) -> bucket (packed payload)
// ---------------------------------------------------------------------------
__global__ void hist_dst(const void* __restrict__ ei) {
    int e = blockIdx.x * blockDim.x + threadIdx.x;
    if (e >= E_EDGES) return;
    int src, dst;
    load_edge(ei, e, src, dst);
    atomicAdd(&g_deg[dst], 1);
}
__global__ void scan_one() {
    __shared__ int s[256];
    __shared__ int sh_base;
    int b = blockIdx.x, t = threadIdx.x, i = b * 256 + t;
    int v = (i < N_NODES) ? g_deg[i] : 0;
    s[t] = v;
    __syncthreads();
    for (int o = 1; o < 256; o <<= 1) {
        int u = (t >= o) ? s[t - o] : 0;
        __syncthreads();
        s[t] += u;
        __syncthreads();
    }
    if (t == 255) sh_base = atomicAdd(&g_total, s[255]);
    __syncthreads();
    if (i < N_NODES) {
        int off = sh_base + s[t] - v;
        g_off[i] = off;
        g_cur[i] = off;
    }
}
__global__ void bucket_edges(const void* __restrict__ ei, const float* __restrict__ ew) {
    int e = blockIdx.x * blockDim.x + threadIdx.x;
    if (e >= E_EDGES) return;
    int src, dst;
    load_edge(ei, e, src, dst);
    int pos = atomicAdd(&g_cur[dst], 1);
    g_edge[pos] = make_uint2((unsigned)src, __float_as_uint(ew[e]));
}

// ---------------------------------------------------------------------------
// bf16 hi/lo split helpers
// ---------------------------------------------------------------------------
__device__ __forceinline__ void split1(float v, __nv_bfloat16& h, __nv_bfloat16& l) {
    h = __float2bfloat16(v);
    l = __float2bfloat16(v - __bfloat162float(h));
}
__device__ __forceinline__ void store_split4(float4 a, __nv_bfloat16* ph, __nv_bfloat16* pl) {
    __nv_bfloat16 h0, h1, h2, h3, l0, l1, l2, l3;
    split1(a.x, h0, l0); split1(a.y, h1, l1); split1(a.z, h2, l2); split1(a.w, h3, l3);
    ((__nv_bfloat162*)ph)[0] = __halves2bfloat162(h0, h1);
    ((__nv_bfloat162*)ph)[1] = __halves2bfloat162(h2, h3);
    ((__nv_bfloat162*)pl)[0] = __halves2bfloat162(l0, l1);
    ((__nv_bfloat162*)pl)[1] = __halves2bfloat162(l2, l3);
}

// ---------------------------------------------------------------------------
// Fused prep: x0 split + fp16 copy + 5 weight transpose-splits
// ---------------------------------------------------------------------------
#define PX0   (N_NODES * INC)
#define PW1   (INC * HID)
#define PW2   (HID * HID)
#define PLIN  (2 * HID * OUTC)
#define PWSUM (2 * PW1 + 2 * PW2 + PLIN)
#define PREP_TOTAL (PX0 + PWSUM)

__global__ void prep_all(const float* __restrict__ x0,
                         const float* __restrict__ wr1, const float* __restrict__ wo1,
                         const float* __restrict__ wr2, const float* __restrict__ wo2,
                         const float* __restrict__ lin) {
    long long i = (long long)blockIdx.x * blockDim.x + threadIdx.x;
    if (i >= PREP_TOTAL) return;
    __nv_bfloat16 hh, ll;
    if (i < PX0) {
        float v = x0[i];
        split1(v, hh, ll);
        g_x0h[i] = hh; g_x0l[i] = ll;
        g_x0p[i] = __float2half(v);
        return;
    }
    long long j = i - PX0;
    const float* W; __nv_bfloat16 *th, *tl; int K, M; long long o;
    if (j < PW1)                { W = wr1; th = g_wr1h; tl = g_wr1l; K = INC; M = HID; o = j; }
    else if (j < 2 * PW1)       { W = wo1; th = g_wo1h; tl = g_wo1l; K = INC; M = HID; o = j - PW1; }
    else if (j < 2 * PW1 + PW2) { W = wr2; th = g_wr2h; tl = g_wr2l; K = HID; M = HID; o = j - 2 * PW1; }
    else if (j < 2 * PW1 + 2 * PW2) { W = wo2; th = g_wo2h; tl = g_wo2l; K = HID; M = HID; o = j - 2 * PW1 - PW2; }
    else                        { W = lin; th = g_linh; tl = g_linl; K = 2 * HID; M = OUTC; o = j - 2 * PW1 - 2 * PW2; }
    int k = (int)(o / M), m = (int)(o % M);
    split1(W[o], hh, ll);
    th[(size_t)m * K + k] = hh;
    tl[(size_t)m * K + k] = ll;
}

// ---------------------------------------------------------------------------
// CSR aggregation: warp per dst, 4 edges in flight (uint4 pair loads of the
// packed edge array -> 4 independent row-gathers -> dual accumulator banks).
// ---------------------------------------------------------------------------
__global__ __launch_bounds__(256)
void agg_csr_128(const __half* __restrict__ x,
                 __nv_bfloat16* __restrict__ oh, __nv_bfloat16* __restrict__ ol) {
    int d = blockIdx.x * 8 + (threadIdx.x >> 5);
    if (d >= N_NODES) return;
    int lane = threadIdx.x & 31;
    int beg = g_off[d], end = g_cur[d];
    float4 a0 = make_float4(0.f, 0.f, 0.f, 0.f);
    float4 a1 = make_float4(0.f, 0.f, 0.f, 0.f);

    int k = beg;
    // 4-edge blocks: edges via two 16B pair-loads when aligned, else scalar
    for (; k + 3 < end; k += 4) {
        uint2 e0, e1, e2, e3;
        if ((k & 1) == 0) {
            uint4 q0 = *(const uint4*)&g_edge[k];
            uint4 q1 = *(const uint4*)&g_edge[k + 2];
            e0 = make_uint2(q0.x, q0.y); e1 = make_uint2(q0.z, q0.w);
            e2 = make_uint2(q1.x, q1.y); e3 = make_uint2(q1.z, q1.w);
        } else {
            e0 = g_edge[k]; e1 = g_edge[k + 1]; e2 = g_edge[k + 2]; e3 = g_edge[k + 3];
        }
        // 4 independent row gathers (uint2 = 4 halves per lane, 128-wide row)
        uint2 p0 = ((const uint2*)(x + (size_t)e0.x * INC))[lane];
        uint2 p1 = ((const uint2*)(x + (size_t)e1.x * INC))[lane];
        uint2 p2 = ((const uint2*)(x + (size_t)e2.x * INC))[lane];
        uint2 p3 = ((const uint2*)(x + (size_t)e3.x * INC))[lane];
        float w0 = __uint_as_float(e0.y), w1 = __uint_as_float(e1.y);
        float w2 = __uint_as_float(e2.y), w3 = __uint_as_float(e3.y);
        float2 f;
        f = __half22float2(*(const __half2*)&p0.x); a0.x = fmaf(w0, f.x, a0.x); a0.y = fmaf(w0, f.y, a0.y);
        f = __half22float2(*(const __half2*)&p0.y); a0.z = fmaf(w0, f.x, a0.z); a0.w = fmaf(w0, f.y, a0.w);
        f = __half22float2(*(const __half2*)&p1.x); a1.x = fmaf(w1, f.x, a1.x); a1.y = fmaf(w1, f.y, a1.y);
        f = __half22float2(*(const __half2*)&p1.y); a1.z = fmaf(w1, f.x, a1.z); a1.w = fmaf(w1, f.y, a1.w);
        f = __half22float2(*(const __half2*)&p2.x); a0.x = fmaf(w2, f.x, a0.x); a0.y = fmaf(w2, f.y, a0.y);
        f = __half22float2(*(const __half2*)&p2.y); a0.z = fmaf(w2, f.x, a0.z); a0.w = fmaf(w2, f.y, a0.w);
        f = __half22float2(*(const __half2*)&p3.x); a1.x = fmaf(w3, f.x, a1.x); a1.y = fmaf(w3, f.y, a1.y);
        f = __half22float2(*(const __half2*)&p3.y); a1.z = fmaf(w3, f.x, a1.z); a1.w = fmaf(w3, f.y, a1.w);
    }
    for (; k < end; ++k) {
        uint2 e0 = g_edge[k];
        float w0 = __uint_as_float(e0.y);
        uint2 p0 = ((const uint2*)(x + (size_t)e0.x * INC))[lane];
        float2 f;
        f = __half22float2(*(const __half2*)&p0.x); a0.x = fmaf(w0, f.x, a0.x); a0.y = fmaf(w0, f.y, a0.y);
        f = __half22float2(*(const __half2*)&p0.y); a0.z = fmaf(w0, f.x, a0.z); a0.w = fmaf(w0, f.y, a0.w);
    }
    a0.x += a1.x; a0.y += a1.y; a0.z += a1.z; a0.w += a1.w;
    store_split4(a0, oh + (size_t)d * INC + lane * 4, ol + (size_t)d * INC + lane * 4);
}

__global__ __launch_bounds__(256)
void agg_csr_256h(const __half* __restrict__ x,
                  __nv_bfloat16* __restrict__ oh, __nv_bfloat16* __restrict__ ol) {
    int d = blockIdx.x * 8 + (threadIdx.x >> 5);
    if (d >= N_NODES) return;
    int lane = threadIdx.x & 31;
    int beg = g_off[d], end = g_cur[d];
    float acc0[8], acc1[8];
#pragma unroll
    for (int j = 0; j < 8; ++j) { acc0[j] = 0.f; acc1[j] = 0.f; }

    int k = beg;
    for (; k + 3 < end; k += 4) {
        uint2 e0, e1, e2, e3;
        if ((k & 1) == 0) {
            uint4 q0 = *(const uint4*)&g_edge[k];
            uint4 q1 = *(const uint4*)&g_edge[k + 2];
            e0 = make_uint2(q0.x, q0.y); e1 = make_uint2(q0.z, q0.w);
            e2 = make_uint2(q1.x, q1.y); e3 = make_uint2(q1.z, q1.w);
        } else {
            e0 = g_edge[k]; e1 = g_edge[k + 1]; e2 = g_edge[k + 2]; e3 = g_edge[k + 3];
        }
        // 4 independent row gathers (uint4 = 8 halves per lane, 256-wide row)
        uint4 p0 = ((const uint4*)(x + (size_t)e0.x * HID))[lane];
        uint4 p1 = ((const uint4*)(x + (size_t)e1.x * HID))[lane];
        uint4 p2 = ((const uint4*)(x + (size_t)e2.x * HID))[lane];
        uint4 p3 = ((const uint4*)(x + (size_t)e3.x * HID))[lane];
        float w0 = __uint_as_float(e0.y), w1 = __uint_as_float(e1.y);
        float w2 = __uint_as_float(e2.y), w3 = __uint_as_float(e3.y);
        const __half2* h0 = (const __half2*)&p0;
        const __half2* h1 = (const __half2*)&p1;
        const __half2* h2 = (const __half2*)&p2;
        const __half2* h3 = (const __half2*)&p3;
#pragma unroll
        for (int j = 0; j < 4; ++j) {
            float2 f0 = __half22float2(h0[j]);
            float2 f1 = __half22float2(h1[j]);
            float2 f2 = __half22float2(h2[j]);
            float2 f3 = __half22float2(h3[j]);
            acc0[2 * j]     = fmaf(w0, f0.x, acc0[2 * j]);
            acc0[2 * j + 1] = fmaf(w0, f0.y, acc0[2 * j + 1]);
            acc1[2 * j]     = fmaf(w1, f1.x, acc1[2 * j]);
            acc1[2 * j + 1] = fmaf(w1, f1.y, acc1[2 * j + 1]);
            acc0[2 * j]     = fmaf(w2, f2.x, acc0[2 * j]);
            acc0[2 * j + 1] = fmaf(w2, f2.y, acc0[2 * j + 1]);
            acc1[2 * j]     = fmaf(w3, f3.x, acc1[2 * j]);
            acc1[2 * j + 1] = fmaf(w3, f3.y, acc1[2 * j + 1]);
        }
    }
    for (; k < end; ++k) {
        uint2 e0 = g_edge[k];
        float w0 = __uint_as_float(e0.y);
        uint4 p0 = ((const uint4*)(x + (size_t)e0.x * HID))[lane];
        const __half2* h0 = (const __half2*)&p0;
#pragma unroll
        for (int j = 0; j < 4; ++j) {
            float2 f0 = __half22float2(h0[j]);
            acc0[2 * j]     = fmaf(w0, f0.x, acc0[2 * j]);
            acc0[2 * j + 1] = fmaf(w0, f0.y, acc0[2 * j + 1]);
        }
    }
#pragma unroll
    for (int j = 0; j < 8; ++j) acc0[j] += acc1[j];
    float4 a0 = make_float4(acc0[0], acc0[1], acc0[2], acc0[3]);
    float4 a1 = make_float4(acc0[4], acc0[5], acc0[6], acc0[7]);
    size_t o = (size_t)d * HID + lane * 8;
    store_split4(a0, oh + o,     ol + o);
    store_split4(a1, oh + o + 4, ol + o + 4);
}

// ---------------------------------------------------------------------------
// Pipelined bf16 split-precision dual-source GEMM (cp.async, 2 stages)
// ---------------------------------------------------------------------------
template <int BN>
__global__ __launch_bounds__(256)
void gemm_mma(const __nv_bfloat16* __restrict__ A1h, const __nv_bfloat16* __restrict__ A1l, int K1,
              const __nv_bfloat16* __restrict__ A2h, const __nv_bfloat16* __restrict__ A2l, int K2,
              const __nv_bfloat16* __restrict__ B1h, const __nv_bfloat16* __restrict__ B1l, int pb1,
              const __nv_bfloat16* __restrict__ B2h, const __nv_bfloat16* __restrict__ B2l, int pb2,
              const float* __restrict__ bias,
              float* __restrict__ outF, __half* __restrict__ outP,
              __nv_bfloat16* __restrict__ outH, __nv_bfloat16* __restrict__ outL,
              int Mout, int doRelu) {
    constexpr int NG = BN / 16;
    constexpr int NQ = BN / 32;
    constexpr int A_ELE = 128 * 32;
    constexpr int B_ELE = BN * 32;
    constexpr int STG = 2 * A_ELE + 2 * B_ELE;

    extern __shared__ __align__(16) __nv_bfloat16 sm[];
    uint32_t base0 = smem_u32(sm);

    int tid = threadIdx.x, wid = tid >> 5, lane = tid & 31;
    int wm = (wid & 3) * 32;
    int wn = (wid >> 2) * (BN / 2);
    int row0 = blockIdx.x * 128;
    int col0 = blockIdx.y * BN;
    int rowsA = N_NODES - row0; if (rowsA > 128) rowsA = 128;
    int rowsB = Mout - col0;    if (rowsB > BN) rowsB = BN;

    const int nc1 = K1 / 32;
    const int NC = nc1 + K2 / 32;

    auto stage_chunk = [&](int c) {
        const __nv_bfloat16 *Ah, *Al, *Bh, *Bl;
        int pa, pb, kcol;
        if (c < nc1) { Ah = A1h; Al = A1l; pa = K1; Bh = B1h; Bl = B1l; pb = pb1; kcol = c * 32; }
        else         { Ah = A2h; Al = A2l; pa = K2; Bh = B2h; Bl = B2l; pb = pb2; kcol = (c - nc1) * 32; }
        Ah += (size_t)row0 * pa; Al += (size_t)row0 * pa;
        Bh += (size_t)col0 * pb; Bl += (size_t)col0 * pb;
        uint32_t sb = base0 + (uint32_t)(c & 1) * STG * 2;
        for (int U = tid; U < 512; U += 256) {
            int r = U >> 2, u = U & 3;
            int up = u ^ ((r >> 1) & 3);
            int rs = (r < rowsA) ? r : 0;
            int sz = (r < rowsA) ? 16 : 0;
            uint32_t da = sb + (uint32_t)(r * 4 + up) * 16u;
            cp16(da,             Ah + (size_t)rs * pa + kcol + u * 8, sz);
            cp16(da + A_ELE * 2, Al + (size_t)rs * pa + kcol + u * 8, sz);
        }
        uint32_t bb = sb + 2u * (2 * A_ELE);
        for (int U = tid; U < BN * 4; U += 256) {
            int r = U >> 2, u = U & 3;
            int up = u ^ ((r >> 1) & 3);
            int rs = (r < rowsB) ? r : 0;
            int sz = (r < rowsB) ? 16 : 0;
            uint32_t da = bb + (uint32_t)(r * 4 + up) * 16u;
            cp16(da,             Bh + (size_t)rs * pb + kcol + u * 8, sz);
            cp16(da + B_ELE * 2, Bl + (size_t)rs * pb + kcol + u * 8, sz);
        }
    };

    float acc[2][NG][4];
#pragma unroll
    for (int i = 0; i < 2; ++i)
#pragma unroll
        for (int j = 0; j < NG; ++j)
#pragma unroll
            for (int q = 0; q < 4; ++q) acc[i][j][q] = 0.f;

    stage_chunk(0);
    asm volatile("cp.async.commit_group;" ::: "memory");

    for (int c = 0; c < NC; ++c) {
        if (c + 1 < NC) {
            stage_chunk(c + 1);
            asm volatile("cp.async.commit_group;" ::: "memory");
            asm volatile("cp.async.wait_group 1;" ::: "memory");
        } else {
            asm volatile("cp.async.wait_group 0;" ::: "memory");
        }
        __syncthreads();

        uint32_t sb = base0 + (uint32_t)(c & 1) * STG * 2;
        uint32_t bAh = sb, bAl = sb + A_ELE * 2;
        uint32_t bBh = sb + 2u * (2 * A_ELE), bBl = bBh + B_ELE * 2;

#pragma unroll
        for (int ks = 0; ks < 2; ++ks) {
            int ksu = ks * 2;
            uint32_t fah[2][4], fal[2][4];
#pragma unroll
            for (int mt = 0; mt < 2; ++mt) {
                int r = wm + mt * 16 + (lane & 15);
                int u = ksu + (lane >> 4);
                ldsm4(tile_addr(bAh, r, u), fah[mt][0], fah[mt][1], fah[mt][2], fah[mt][3]);
                ldsm4(tile_addr(bAl, r, u), fal[mt][0], fal[mt][1], fal[mt][2], fal[mt][3]);
            }
            uint32_t fbh[NQ][4], fbl[NQ][4];
#pragma unroll
            for (int q = 0; q < NQ; ++q) {
                int r = wn + q * 16 + (lane & 7) + ((lane & 16) ? 8 : 0);
                int u = ksu + ((lane >> 3) & 1);
                ldsm4(tile_addr(bBh, r, u), fbh[q][0], fbh[q][1], fbh[q][2], fbh[q][3]);
                ldsm4(tile_addr(bBl, r, u), fbl[q][0], fbl[q][1], fbl[q][2], fbl[q][3]);
            }
#pragma unroll
            for (int mt = 0; mt < 2; ++mt)
#pragma unroll
                for (int ng = 0; ng < NG; ++ng) {
                    const uint32_t* bpH = &fbh[ng >> 1][(ng & 1) * 2];
                    const uint32_t* bpL = &fbl[ng >> 1][(ng & 1) * 2];
                    mma16816(acc[mt][ng], fah[mt], bpH);
                    mma16816(acc[mt][ng], fah[mt], bpL);
                    mma16816(acc[mt][ng], fal[mt], bpH);
                }
        }
        __syncthreads();
    }

    // Epilogue
#pragma unroll
    for (int mt = 0; mt < 2; ++mt) {
        int rg = row0 + wm + mt * 16 + (lane >> 2);
#pragma unroll
        for (int half = 0; half < 2; ++half) {
            int r = rg + half * 8;
            if (r >= N_NODES) continue;
#pragma unroll
            for (int ng = 0; ng < NG; ++ng) {
                int c0 = col0 + wn + ng * 8 + (lane & 3) * 2;
#pragma unroll
                for (int q = 0; q < 2; ++q) {
                    int c = c0 + q;
                    if (c >= Mout) continue;
                    float v = acc[mt][ng][half * 2 + q] + bias[c];
                    if (doRelu) v = fmaxf(v, 0.f);
                    size_t idx = (size_t)r * Mout + c;
                    if (outF) outF[idx] = v;
                    if (outP) outP[idx] = __float2half(v);
                    if (outH) {
                        __nv_bfloat16 hh, ll;
                        split1(v, hh, ll);
                        outH[idx] = hh;
                        outL[idx] = ll;
                    }
                }
            }
        }
    }
}

// ---------------------------------------------------------------------------
extern "C" void kernel_launch(void* const* d_in, const int* in_sizes, int n_in,
                              void* d_out, int out_size) {
    const float* x0      = (const float*)d_in[0];
    const void*  ei      = d_in[1];
    const float* ew      = (const float*)d_in[2];
    const float* w_rel1  = (const float*)d_in[3];
    const float* b1      = (const float*)d_in[4];
    const float* w_root1 = (const float*)d_in[5];
    const float* w_rel2  = (const float*)d_in[6];
    const float* b2      = (const float*)d_in[7];
    const float* w_root2 = (const float*)d_in[8];
    const float* lin_w   = (const float*)d_in[9];
    const float* lin_b   = (const float*)d_in[10];
    float*       out     = (float*)d_out;

#define SYM(p, s) cudaGetSymbolAddress((void**)&p, s)
    __nv_bfloat16 *x0h, *x0l, *a1h, *a1l, *x1h, *x1l, *a2h, *a2l, *x2h, *x2l;
    __nv_bfloat16 *wr1h, *wr1l, *wo1h, *wo1l, *wr2h, *wr2l, *wo2h, *wo2l, *linh, *linl;
    __half *x0p, *x1p;
    SYM(x0h, g_x0h); SYM(x0l, g_x0l); SYM(x0p, g_x0p);
    SYM(a1h, g_a1h); SYM(a1l, g_a1l);
    SYM(x1p, g_x1p); SYM(x1h, g_x1h); SYM(x1l, g_x1l);
    SYM(a2h, g_a2h); SYM(a2l, g_a2l); SYM(x2h, g_x2h); SYM(x2l, g_x2l);
    SYM(wr1h, g_wr1h); SYM(wr1l, g_wr1l); SYM(wo1h, g_wo1h); SYM(wo1l, g_wo1l);
    SYM(wr2h, g_wr2h); SYM(wr2l, g_wr2l); SYM(wo2h, g_wo2h); SYM(wo2l, g_wo2l);
    SYM(linh, g_linh); SYM(linl, g_linl);
#undef SYM

    const int SM128 = 2 * (2 * 128 * 32 + 2 * 128 * 32) * 2;  // 65536 B
    const int SM64  = 2 * (2 * 128 * 32 + 2 * 64 * 32) * 2;   // 49152 B
    cudaFuncSetAttribute(gemm_mma<128>, cudaFuncAttributeMaxDynamicSharedMemorySize, SM128);
    cudaFuncSetAttribute(gemm_mma<64>,  cudaFuncAttributeMaxDynamicSharedMemorySize, SM64);

    const int eblk = (E_EDGES + 255) / 256;
    const int wblk = (N_NODES + 7) / 8;
    const int gblk = (N_NODES + 127) / 128;   // 391

    // 0) detect + deg zero, then fused prep (serial, single stream)
    detect_and_zero<<<NB_SCAN, 256>>>(ei);
    prep_all<<<(PREP_TOTAL + 255) / 256, 256>>>(x0, w_rel1, w_root1, w_rel2, w_root2, lin_w);

    // 1) CSR build
    hist_dst<<<eblk, 256>>>(ei);
    scan_one<<<NB_SCAN, 256>>>();
    bucket_edges<<<eblk, 256>>>(ei, ew);

    // 2) layer 1
    agg_csr_128<<<wblk, 256>>>(x0p, a1h, a1l);
    gemm_mma<128><<<dim3(gblk, 2), 256, SM128>>>(a1h, a1l, INC, x0h, x0l, INC,
                                                 wr1h, wr1l, INC, wo1h, wo1l, INC,
                                                 b1, (float*)0, x1p, x1h, x1l, HID, 1);
    // 3) layer 2
    agg_csr_256h<<<wblk, 256>>>(x1p, a2h, a2l);
    gemm_mma<128><<<dim3(gblk, 2), 256, SM128>>>(a2h, a2l, HID, x1h, x1l, HID,
                                                 wr2h, wr2l, HID, wo2h, wo2l, HID,
                                                 b2, (float*)0, (__half*)0, x2h, x2l, HID, 1);
    // 4) head
    gemm_mma<64><<<dim3(gblk, 1), 256, SM64>>>(x1h, x1l, HID, x2h, x2l, HID,
                                               linh, linl, 2 * HID, linh + HID, linl + HID, 2 * HID,
                                               lin_b, out, (__half*)0,
                                               (__nv_bfloat16*)0, (__nv_bfloat16*)0,
                                               OUTC, 0);
}

// round 14
// speedup vs baseline: 1.4023x; 1.3995x over previous
#include <cuda_runtime.h>
#include <cuda_fp16.h>
#include <stdint.h>

#define N_NODES 50000
#define E_EDGES 800000
#define INC 128
#define HID 256
#define OUTC 51
#define NB_SCAN 196   // ceil(50000/256)

// ---------------------------------------------------------------------------
// Scratch (static device globals -- allocation-free per harness rules)
// All activations fp16; weights fp16 2-term split (hi + lo), transposed.
// ---------------------------------------------------------------------------
__device__ __align__(16) __half g_x0p[N_NODES * INC];
__device__ __align__(16) __half g_a1p[N_NODES * INC];
__device__ __align__(16) __half g_x1p[N_NODES * HID];
__device__ __align__(16) __half g_a2p[N_NODES * HID];
__device__ __align__(16) __half g_x2p[N_NODES * HID];
__device__ __align__(16) __half g_wr1h[HID * INC],  g_wr1l[HID * INC];
__device__ __align__(16) __half g_wo1h[HID * INC],  g_wo1l[HID * INC];
__device__ __align__(16) __half g_wr2h[HID * HID],  g_wr2l[HID * HID];
__device__ __align__(16) __half g_wo2h[HID * HID],  g_wo2l[HID * HID];
__device__ __align__(16) __half g_linh[OUTC * 2 * HID], g_linl[OUTC * 2 * HID];
// CSR (payload packed: x = src, y = weight bits)
__device__ int   g_deg[N_NODES];
__device__ int   g_off[N_NODES];
__device__ int   g_cur[N_NODES];
__device__ __align__(16) uint2 g_edge[E_EDGES + 4];
__device__ int   g_total;
__device__ int   g_idx_is64;

// ---------------------------------------------------------------------------
// PTX helpers (baseline PTX only)
// ---------------------------------------------------------------------------
__device__ __forceinline__ uint32_t smem_u32(const void* p) {
    uint32_t a;
    asm("{ .reg .u64 t; cvta.to.shared.u64 t, %1; cvt.u32.u64 %0, t; }" : "=r"(a) : "l"(p));
    return a;
}
__device__ __forceinline__ uint32_t h2_as_u32(__half2 h) {
    uint32_t u;
    memcpy(&u, &h, 4);
    return u;
}
__device__ __forceinline__ void ldsm4(uint32_t addr, uint32_t& r0, uint32_t& r1,
                                      uint32_t& r2, uint32_t& r3) {
    asm volatile("ldmatrix.sync.aligned.m8n8.x4.shared.b16 {%0,%1,%2,%3}, [%4];"
                 : "=r"(r0), "=r"(r1), "=r"(r2), "=r"(r3) : "r"(addr));
}
__device__ __forceinline__ void mma16816h(float* c, const uint32_t* a, const uint32_t* b) {
    asm volatile("mma.sync.aligned.m16n8k16.row.col.f32.f16.f16.f32 "
                 "{%0,%1,%2,%3}, {%4,%5,%6,%7}, {%8,%9}, {%0,%1,%2,%3};"
                 : "+f"(c[0]), "+f"(c[1]), "+f"(c[2]), "+f"(c[3])
                 : "r"(a[0]), "r"(a[1]), "r"(a[2]), "r"(a[3]), "r"(b[0]), "r"(b[1]));
}
__device__ __forceinline__ uint32_t tile_addr(uint32_t base, int r, int u) {
    int up = u ^ ((r >> 1) & 3);
    return base + (uint32_t)(r * 4 + up) * 16u;
}
__device__ __forceinline__ void cp16(uint32_t daddr, const void* src, int sz) {
    asm volatile("cp.async.cg.shared.global [%0], [%1], 16, %2;"
                 :: "r"(daddr), "l"(src), "r"(sz) : "memory");
}

// ---------------------------------------------------------------------------
// dtype detect + zero scan base + zero deg
// ---------------------------------------------------------------------------
__global__ void detect_and_zero(const void* __restrict__ ei) {
    int i = blockIdx.x * blockDim.x + threadIdx.x;
    if (i < N_NODES) g_deg[i] = 0;
    if (blockIdx.x == 0 && threadIdx.x < 32) {
        int t = threadIdx.x;
        const long long* p = (const long long*)ei;
        int bad = 0;
        for (int k = t; k < 256; k += 32) {
            long long v = p[k];
            if (v < 0 || v >= N_NODES) bad = 1;
        }
        unsigned m = __ballot_sync(0xffffffffu, bad);
        if (t == 0) { g_idx_is64 = (m == 0u); g_total = 0; }
    }
}
__device__ __forceinline__ void load_edge(const void* ei, int e, int& src, int& dst) {
    if (g_idx_is64) {
        src = (int)((const long long*)ei)[e];
        dst = (int)((const long long*)ei)[E_EDGES + e];
    } else {
        src = ((const int*)ei)[e];
        dst = ((const int*)ei)[E_EDGES + e];
    }
}

// ---------------------------------------------------------------------------
// CSR build: hist -> one-pass scan -> bucket
// ---------------------------------------------------------------------------
__global__ void hist_dst(const void* __restrict__ ei) {
    int e = blockIdx.x * blockDim.x + threadIdx.x;
    if (e >= E_EDGES) return;
    int src, dst;
    load_edge(ei, e, src, dst);
    atomicAdd(&g_deg[dst], 1);
}
__global__ void scan_one() {
    __shared__ int s[256];
    __shared__ int sh_base;
    int b = blockIdx.x, t = threadIdx.x, i = b * 256 + t;
    int v = (i < N_NODES) ? g_deg[i] : 0;
    s[t] = v;
    __syncthreads();
    for (int o = 1; o < 256; o <<= 1) {
        int u = (t >= o) ? s[t - o] : 0;
        __syncthreads();
        s[t] += u;
        __syncthreads();
    }
    if (t == 255) sh_base = atomicAdd(&g_total, s[255]);
    __syncthreads();
    if (i < N_NODES) {
        int off = sh_base + s[t] - v;
        g_off[i] = off;
        g_cur[i] = off;
    }
}
__global__ void bucket_edges(const void* __restrict__ ei, const float* __restrict__ ew) {
    int e = blockIdx.x * blockDim.x + threadIdx.x;
    if (e >= E_EDGES) return;
    int src, dst;
    load_edge(ei, e, src, dst);
    int pos = atomicAdd(&g_cur[dst], 1);
    g_edge[pos] = make_uint2((unsigned)src, __float_as_uint(ew[e]));
}

// ---------------------------------------------------------------------------
// Fused prep: x0 -> fp16, weights -> transposed fp16 hi/lo split
// ---------------------------------------------------------------------------
#define PX0   (N_NODES * INC)
#define PW1   (INC * HID)
#define PW2   (HID * HID)
#define PLIN  (2 * HID * OUTC)
#define PWSUM (2 * PW1 + 2 * PW2 + PLIN)
#define PREP_TOTAL (PX0 + PWSUM)

__global__ void prep_all(const float* __restrict__ x0,
                         const float* __restrict__ wr1, const float* __restrict__ wo1,
                         const float* __restrict__ wr2, const float* __restrict__ wo2,
                         const float* __restrict__ lin) {
    long long i = (long long)blockIdx.x * blockDim.x + threadIdx.x;
    if (i >= PREP_TOTAL) return;
    if (i < PX0) {
        g_x0p[i] = __float2half(x0[i]);
        return;
    }
    long long j = i - PX0;
    const float* W; __half *th, *tl; int K, M; long long o;
    if (j < PW1)                { W = wr1; th = g_wr1h; tl = g_wr1l; K = INC; M = HID; o = j; }
    else if (j < 2 * PW1)       { W = wo1; th = g_wo1h; tl = g_wo1l; K = INC; M = HID; o = j - PW1; }
    else if (j < 2 * PW1 + PW2) { W = wr2; th = g_wr2h; tl = g_wr2l; K = HID; M = HID; o = j - 2 * PW1; }
    else if (j < 2 * PW1 + 2 * PW2) { W = wo2; th = g_wo2h; tl = g_wo2l; K = HID; M = HID; o = j - 2 * PW1 - PW2; }
    else                        { W = lin; th = g_linh; tl = g_linl; K = 2 * HID; M = OUTC; o = j - 2 * PW1 - 2 * PW2; }
    int k = (int)(o / M), m = (int)(o % M);
    float w = W[o];
    __half wh = __float2half(w);
    __half wl = __float2half(w - __half2float(wh));
    th[(size_t)m * K + k] = wh;
    tl[(size_t)m * K + k] = wl;
}

// ---------------------------------------------------------------------------
// CSR aggregation: warp per dst, 4 edges in flight, fp32 accum, fp16 store
// ---------------------------------------------------------------------------
__global__ __launch_bounds__(256)
void agg_csr_128(const __half* __restrict__ x, __half* __restrict__ o) {
    int d = blockIdx.x * 8 + (threadIdx.x >> 5);
    if (d >= N_NODES) return;
    int lane = threadIdx.x & 31;
    int beg = g_off[d], end = g_cur[d];
    float4 a0 = make_float4(0.f, 0.f, 0.f, 0.f);
    float4 a1 = make_float4(0.f, 0.f, 0.f, 0.f);
    int k = beg;
    for (; k + 3 < end; k += 4) {
        uint2 e0, e1, e2, e3;
        if ((k & 1) == 0) {
            uint4 q0 = *(const uint4*)&g_edge[k];
            uint4 q1 = *(const uint4*)&g_edge[k + 2];
            e0 = make_uint2(q0.x, q0.y); e1 = make_uint2(q0.z, q0.w);
            e2 = make_uint2(q1.x, q1.y); e3 = make_uint2(q1.z, q1.w);
        } else {
            e0 = g_edge[k]; e1 = g_edge[k + 1]; e2 = g_edge[k + 2]; e3 = g_edge[k + 3];
        }
        uint2 p0 = ((const uint2*)(x + (size_t)e0.x * INC))[lane];
        uint2 p1 = ((const uint2*)(x + (size_t)e1.x * INC))[lane];
        uint2 p2 = ((const uint2*)(x + (size_t)e2.x * INC))[lane];
        uint2 p3 = ((const uint2*)(x + (size_t)e3.x * INC))[lane];
        float w0 = __uint_as_float(e0.y), w1 = __uint_as_float(e1.y);
        float w2 = __uint_as_float(e2.y), w3 = __uint_as_float(e3.y);
        float2 f;
        f = __half22float2(*(const __half2*)&p0.x); a0.x = fmaf(w0, f.x, a0.x); a0.y = fmaf(w0, f.y, a0.y);
        f = __half22float2(*(const __half2*)&p0.y); a0.z = fmaf(w0, f.x, a0.z); a0.w = fmaf(w0, f.y, a0.w);
        f = __half22float2(*(const __half2*)&p1.x); a1.x = fmaf(w1, f.x, a1.x); a1.y = fmaf(w1, f.y, a1.y);
        f = __half22float2(*(const __half2*)&p1.y); a1.z = fmaf(w1, f.x, a1.z); a1.w = fmaf(w1, f.y, a1.w);
        f = __half22float2(*(const __half2*)&p2.x); a0.x = fmaf(w2, f.x, a0.x); a0.y = fmaf(w2, f.y, a0.y);
        f = __half22float2(*(const __half2*)&p2.y); a0.z = fmaf(w2, f.x, a0.z); a0.w = fmaf(w2, f.y, a0.w);
        f = __half22float2(*(const __half2*)&p3.x); a1.x = fmaf(w3, f.x, a1.x); a1.y = fmaf(w3, f.y, a1.y);
        f = __half22float2(*(const __half2*)&p3.y); a1.z = fmaf(w3, f.x, a1.z); a1.w = fmaf(w3, f.y, a1.w);
    }
    for (; k < end; ++k) {
        uint2 e0 = g_edge[k];
        float w0 = __uint_as_float(e0.y);
        uint2 p0 = ((const uint2*)(x + (size_t)e0.x * INC))[lane];
        float2 f;
        f = __half22float2(*(const __half2*)&p0.x); a0.x = fmaf(w0, f.x, a0.x); a0.y = fmaf(w0, f.y, a0.y);
        f = __half22float2(*(const __half2*)&p0.y); a0.z = fmaf(w0, f.x, a0.z); a0.w = fmaf(w0, f.y, a0.w);
    }
    a0.x += a1.x; a0.y += a1.y; a0.z += a1.z; a0.w += a1.w;
    uint2 st;
    st.x = h2_as_u32(__floats2half2_rn(a0.x, a0.y));
    st.y = h2_as_u32(__floats2half2_rn(a0.z, a0.w));
    *(uint2*)(o + (size_t)d * INC + lane * 4) = st;
}

__global__ __launch_bounds__(256)
void agg_csr_256(const __half* __restrict__ x, __half* __restrict__ o) {
    int d = blockIdx.x * 8 + (threadIdx.x >> 5);
    if (d >= N_NODES) return;
    int lane = threadIdx.x & 31;
    int beg = g_off[d], end = g_cur[d];
    float acc0[8], acc1[8];
#pragma unroll
    for (int j = 0; j < 8; ++j) { acc0[j] = 0.f; acc1[j] = 0.f; }
    int k = beg;
    for (; k + 3 < end; k += 4) {
        uint2 e0, e1, e2, e3;
        if ((k & 1) == 0) {
            uint4 q0 = *(const uint4*)&g_edge[k];
            uint4 q1 = *(const uint4*)&g_edge[k + 2];
            e0 = make_uint2(q0.x, q0.y); e1 = make_uint2(q0.z, q0.w);
            e2 = make_uint2(q1.x, q1.y); e3 = make_uint2(q1.z, q1.w);
        } else {
            e0 = g_edge[k]; e1 = g_edge[k + 1]; e2 = g_edge[k + 2]; e3 = g_edge[k + 3];
        }
        uint4 p0 = ((const uint4*)(x + (size_t)e0.x * HID))[lane];
        uint4 p1 = ((const uint4*)(x + (size_t)e1.x * HID))[lane];
        uint4 p2 = ((const uint4*)(x + (size_t)e2.x * HID))[lane];
        uint4 p3 = ((const uint4*)(x + (size_t)e3.x * HID))[lane];
        float w0 = __uint_as_float(e0.y), w1 = __uint_as_float(e1.y);
        float w2 = __uint_as_float(e2.y), w3 = __uint_as_float(e3.y);
        const __half2* h0 = (const __half2*)&p0;
        const __half2* h1 = (const __half2*)&p1;
        const __half2* h2 = (const __half2*)&p2;
        const __half2* h3 = (const __half2*)&p3;
#pragma unroll
        for (int j = 0; j < 4; ++j) {
            float2 f0 = __half22float2(h0[j]);
            float2 f1 = __half22float2(h1[j]);
            float2 f2 = __half22float2(h2[j]);
            float2 f3 = __half22float2(h3[j]);
            acc0[2 * j]     = fmaf(w0, f0.x, acc0[2 * j]);
            acc0[2 * j + 1] = fmaf(w0, f0.y, acc0[2 * j + 1]);
            acc1[2 * j]     = fmaf(w1, f1.x, acc1[2 * j]);
            acc1[2 * j + 1] = fmaf(w1, f1.y, acc1[2 * j + 1]);
            acc0[2 * j]     = fmaf(w2, f2.x, acc0[2 * j]);
            acc0[2 * j + 1] = fmaf(w2, f2.y, acc0[2 * j + 1]);
            acc1[2 * j]     = fmaf(w3, f3.x, acc1[2 * j]);
            acc1[2 * j + 1] = fmaf(w3, f3.y, acc1[2 * j + 1]);
        }
    }
    for (; k < end; ++k) {
        uint2 e0 = g_edge[k];
        float w0 = __uint_as_float(e0.y);
        uint4 p0 = ((const uint4*)(x + (size_t)e0.x * HID))[lane];
        const __half2* h0 = (const __half2*)&p0;
#pragma unroll
        for (int j = 0; j < 4; ++j) {
            float2 f0 = __half22float2(h0[j]);
            acc0[2 * j]     = fmaf(w0, f0.x, acc0[2 * j]);
            acc0[2 * j + 1] = fmaf(w0, f0.y, acc0[2 * j + 1]);
        }
    }
    uint4 st;
    st.x = h2_as_u32(__floats2half2_rn(acc0[0] + acc1[0], acc0[1] + acc1[1]));
    st.y = h2_as_u32(__floats2half2_rn(acc0[2] + acc1[2], acc0[3] + acc1[3]));
    st.z = h2_as_u32(__floats2half2_rn(acc0[4] + acc1[4], acc0[5] + acc1[5]));
    st.w = h2_as_u32(__floats2half2_rn(acc0[6] + acc1[6], acc0[7] + acc1[7]));
    *(uint4*)(o + (size_t)d * HID + lane * 8) = st;
}

// ---------------------------------------------------------------------------
// fp16 dual-source GEMM, weights 2-term split: D = A1@(W1h+W1l) + A2@(W2h+W2l)
// A fp16 single tile; 2 MMAs per (mt,ng); cp.async 2-stage pipeline.
// ---------------------------------------------------------------------------
template <int BN>
__global__ __launch_bounds__(256, 2)
void gemm_h(const __half* __restrict__ A1, int K1,
            const __half* __restrict__ A2, int K2,
            const __half* __restrict__ B1h, const __half* __restrict__ B1l, int pb1,
            const __half* __restrict__ B2h, const __half* __restrict__ B2l, int pb2,
            const float* __restrict__ bias,
            float* __restrict__ outF, __half* __restrict__ outP,
            int Mout, int doRelu) {
    constexpr int NG = BN / 16;
    constexpr int NQ = BN / 32;
    constexpr int A_ELE = 128 * 32;          // halves per A tile
    constexpr int B_ELE = BN * 32;           // halves per B tile
    constexpr int STG = A_ELE + 2 * B_ELE;   // halves per stage

    extern __shared__ __align__(16) __half smh[];
    uint32_t base0 = smem_u32(smh);

    int tid = threadIdx.x, wid = tid >> 5, lane = tid & 31;
    int wm = (wid & 3) * 32;
    int wn = (wid >> 2) * (BN / 2);
    int row0 = blockIdx.x * 128;
    int col0 = blockIdx.y * BN;
    int rowsA = N_NODES - row0; if (rowsA > 128) rowsA = 128;
    int rowsB = Mout - col0;    if (rowsB > BN) rowsB = BN;

    const int nc1 = K1 / 32;
    const int NC = nc1 + K2 / 32;

    auto stage_chunk = [&](int c) {
        const __half *A, *Bh, *Bl;
        int pa, pb, kcol;
        if (c < nc1) { A = A1; pa = K1; Bh = B1h; Bl = B1l; pb = pb1; kcol = c * 32; }
        else         { A = A2; pa = K2; Bh = B2h; Bl = B2l; pb = pb2; kcol = (c - nc1) * 32; }
        A  += (size_t)row0 * pa;
        Bh += (size_t)col0 * pb;
        Bl += (size_t)col0 * pb;
        uint32_t sb = base0 + (uint32_t)(c & 1) * STG * 2;
        for (int U = tid; U < 512; U += 256) {
            int r = U >> 2, u = U & 3;
            int up = u ^ ((r >> 1) & 3);
            int rs = (r < rowsA) ? r : 0;
            int sz = (r < rowsA) ? 16 : 0;
            cp16(sb + (uint32_t)(r * 4 + up) * 16u, A + (size_t)rs * pa + kcol + u * 8, sz);
        }
        uint32_t bb = sb + A_ELE * 2;
        for (int U = tid; U < BN * 4; U += 256) {
            int r = U >> 2, u = U & 3;
            int up = u ^ ((r >> 1) & 3);
            int rs = (r < rowsB) ? r : 0;
            int sz = (r < rowsB) ? 16 : 0;
            uint32_t da = bb + (uint32_t)(r * 4 + up) * 16u;
            cp16(da,             Bh + (size_t)rs * pb + kcol + u * 8, sz);
            cp16(da + B_ELE * 2, Bl + (size_t)rs * pb + kcol + u * 8, sz);
        }
    };

    float acc[2][NG][4];
#pragma unroll
    for (int i = 0; i < 2; ++i)
#pragma unroll
        for (int j = 0; j < NG; ++j)
#pragma unroll
            for (int q = 0; q < 4; ++q) acc[i][j][q] = 0.f;

    stage_chunk(0);
    asm volatile("cp.async.commit_group;" ::: "memory");

    for (int c = 0; c < NC; ++c) {
        if (c + 1 < NC) {
            stage_chunk(c + 1);
            asm volatile("cp.async.commit_group;" ::: "memory");
            asm volatile("cp.async.wait_group 1;" ::: "memory");
        } else {
            asm volatile("cp.async.wait_group 0;" ::: "memory");
        }
        __syncthreads();

        uint32_t sb  = base0 + (uint32_t)(c & 1) * STG * 2;
        uint32_t bA  = sb;
        uint32_t bBh = sb + A_ELE * 2;
        uint32_t bBl = bBh + B_ELE * 2;

#pragma unroll
        for (int ks = 0; ks < 2; ++ks) {
            int ksu = ks * 2;
            uint32_t fa[2][4];
#pragma unroll
            for (int mt = 0; mt < 2; ++mt) {
                int r = wm + mt * 16 + (lane & 15);
                int u = ksu + (lane >> 4);
                ldsm4(tile_addr(bA, r, u), fa[mt][0], fa[mt][1], fa[mt][2], fa[mt][3]);
            }
            uint32_t fbh[NQ][4], fbl[NQ][4];
#pragma unroll
            for (int q = 0; q < NQ; ++q) {
                int r = wn + q * 16 + (lane & 7) + ((lane & 16) ? 8 : 0);
                int u = ksu + ((lane >> 3) & 1);
                ldsm4(tile_addr(bBh, r, u), fbh[q][0], fbh[q][1], fbh[q][2], fbh[q][3]);
                ldsm4(tile_addr(bBl, r, u), fbl[q][0], fbl[q][1], fbl[q][2], fbl[q][3]);
            }
#pragma unroll
            for (int mt = 0; mt < 2; ++mt)
#pragma unroll
                for (int ng = 0; ng < NG; ++ng) {
                    const uint32_t* bpH = &fbh[ng >> 1][(ng & 1) * 2];
                    const uint32_t* bpL = &fbl[ng >> 1][(ng & 1) * 2];
                    mma16816h(acc[mt][ng], fa[mt], bpH);
                    mma16816h(acc[mt][ng], fa[mt], bpL);
                }
        }
        __syncthreads();
    }

    // Epilogue
#pragma unroll
    for (int mt = 0; mt < 2; ++mt) {
        int rg = row0 + wm + mt * 16 + (lane >> 2);
#pragma unroll
        for (int half = 0; half < 2; ++half) {
            int r = rg + half * 8;
            if (r >= N_NODES) continue;
#pragma unroll
            for (int ng = 0; ng < NG; ++ng) {
                int c0 = col0 + wn + ng * 8 + (lane & 3) * 2;
#pragma unroll
                for (int q = 0; q < 2; ++q) {
                    int c = c0 + q;
                    if (c >= Mout) continue;
                    float v = acc[mt][ng][half * 2 + q] + bias[c];
                    if (doRelu) v = fmaxf(v, 0.f);
                    size_t idx = (size_t)r * Mout + c;
                    if (outF) outF[idx] = v;
                    if (outP) outP[idx] = __float2half(v);
                }
            }
        }
    }
}

// ---------------------------------------------------------------------------
extern "C" void kernel_launch(void* const* d_in, const int* in_sizes, int n_in,
                              void* d_out, int out_size) {
    const float* x0      = (const float*)d_in[0];
    const void*  ei      = d_in[1];
    const float* ew      = (const float*)d_in[2];
    const float* w_rel1  = (const float*)d_in[3];
    const float* b1      = (const float*)d_in[4];
    const float* w_root1 = (const float*)d_in[5];
    const float* w_rel2  = (const float*)d_in[6];
    const float* b2      = (const float*)d_in[7];
    const float* w_root2 = (const float*)d_in[8];
    const float* lin_w   = (const float*)d_in[9];
    const float* lin_b   = (const float*)d_in[10];
    float*       out     = (float*)d_out;

#define SYM(p, s) cudaGetSymbolAddress((void**)&p, s)
    __half *x0p, *a1p, *x1p, *a2p, *x2p;
    __half *wr1h, *wr1l, *wo1h, *wo1l, *wr2h, *wr2l, *wo2h, *wo2l, *linh, *linl;
    SYM(x0p, g_x0p); SYM(a1p, g_a1p); SYM(x1p, g_x1p);
    SYM(a2p, g_a2p); SYM(x2p, g_x2p);
    SYM(wr1h, g_wr1h); SYM(wr1l, g_wr1l); SYM(wo1h, g_wo1h); SYM(wo1l, g_wo1l);
    SYM(wr2h, g_wr2h); SYM(wr2l, g_wr2l); SYM(wo2h, g_wo2h); SYM(wo2l, g_wo2l);
    SYM(linh, g_linh); SYM(linl, g_linl);
#undef SYM

    // dynamic smem: 2 stages x (A + 2 B) fp16 tiles
    const int SM128 = 2 * (128 * 32 + 2 * 128 * 32) * 2;  // 49152 B
    const int SM64  = 2 * (128 * 32 + 2 * 64 * 32) * 2;   // 32768 B
    cudaFuncSetAttribute(gemm_h<128>, cudaFuncAttributeMaxDynamicSharedMemorySize, SM128);
    cudaFuncSetAttribute(gemm_h<64>,  cudaFuncAttributeMaxDynamicSharedMemorySize, SM64);

    const int eblk = (E_EDGES + 255) / 256;
    const int wblk = (N_NODES + 7) / 8;
    const int gblk = (N_NODES + 127) / 128;   // 391

    // 0) detect + deg zero, fused prep
    detect_and_zero<<<NB_SCAN, 256>>>(ei);
    prep_all<<<(PREP_TOTAL + 255) / 256, 256>>>(x0, w_rel1, w_root1, w_rel2, w_root2, lin_w);

    // 1) CSR build
    hist_dst<<<eblk, 256>>>(ei);
    scan_one<<<NB_SCAN, 256>>>();
    bucket_edges<<<eblk, 256>>>(ei, ew);

    // 2) layer 1
    agg_csr_128<<<wblk, 256>>>(x0p, a1p);
    gemm_h<128><<<dim3(gblk, 2), 256, SM128>>>(a1p, INC, x0p, INC,
                                               wr1h, wr1l, INC, wo1h, wo1l, INC,
                                               b1, (float*)0, x1p, HID, 1);
    // 3) layer 2
    agg_csr_256<<<wblk, 256>>>(x1p, a2p);
    gemm_h<128><<<dim3(gblk, 2), 256, SM128>>>(a2p, HID, x1p, HID,
                                               wr2h, wr2l, HID, wo2h, wo2l, HID,
                                               b2, (float*)0, x2p, HID, 1);
    // 4) head
    gemm_h<64><<<dim3(gblk, 1), 256, SM64>>>(x1p, HID, x2p, HID,
                                             linh, linl, 2 * HID, linh + HID, linl + HID, 2 * HID,
                                             lin_b, out, (__half*)0, OUTC, 0);
}

// round 15
// speedup vs baseline: 1.5586x; 1.1114x over previous
#include <cuda_runtime.h>
#include <cuda_fp16.h>
#include <stdint.h>

#define N_NODES 50000
#define E_EDGES 800000
#define INC 128
#define HID 256
#define OUTC 51
#define NB_SCAN 196   // ceil(50000/256)

// ---------------------------------------------------------------------------
// Scratch (static device globals -- allocation-free per harness rules)
// Activations fp16. Layer weights plain fp16 (hi only); head weights split.
// ---------------------------------------------------------------------------
__device__ __align__(16) __half g_x0p[N_NODES * INC];
__device__ __align__(16) __half g_a1p[N_NODES * INC];
__device__ __align__(16) __half g_x1p[N_NODES * HID];
__device__ __align__(16) __half g_a2p[N_NODES * HID];
__device__ __align__(16) __half g_x2p[N_NODES * HID];
__device__ __align__(16) __half g_wr1h[HID * INC],  g_wr1l[HID * INC];
__device__ __align__(16) __half g_wo1h[HID * INC],  g_wo1l[HID * INC];
__device__ __align__(16) __half g_wr2h[HID * HID],  g_wr2l[HID * HID];
__device__ __align__(16) __half g_wo2h[HID * HID],  g_wo2l[HID * HID];
__device__ __align__(16) __half g_linh[OUTC * 2 * HID], g_linl[OUTC * 2 * HID];
// CSR (payload packed: x = src, y = weight bits)
__device__ int   g_deg[N_NODES];
__device__ int   g_off[N_NODES];
__device__ int   g_cur[N_NODES];
__device__ __align__(16) uint2 g_edge[E_EDGES + 4];
__device__ int   g_total;
__device__ int   g_idx_is64;

// ---------------------------------------------------------------------------
// PTX helpers (baseline PTX only)
// ---------------------------------------------------------------------------
__device__ __forceinline__ uint32_t smem_u32(const void* p) {
    uint32_t a;
    asm("{ .reg .u64 t; cvta.to.shared.u64 t, %1; cvt.u32.u64 %0, t; }" : "=r"(a) : "l"(p));
    return a;
}
__device__ __forceinline__ uint32_t h2_as_u32(__half2 h) {
    uint32_t u;
    memcpy(&u, &h, 4);
    return u;
}
__device__ __forceinline__ void ldsm4(uint32_t addr, uint32_t& r0, uint32_t& r1,
                                      uint32_t& r2, uint32_t& r3) {
    asm volatile("ldmatrix.sync.aligned.m8n8.x4.shared.b16 {%0,%1,%2,%3}, [%4];"
                 : "=r"(r0), "=r"(r1), "=r"(r2), "=r"(r3) : "r"(addr));
}
__device__ __forceinline__ void mma16816h(float* c, const uint32_t* a, const uint32_t* b) {
    asm volatile("mma.sync.aligned.m16n8k16.row.col.f32.f16.f16.f32 "
                 "{%0,%1,%2,%3}, {%4,%5,%6,%7}, {%8,%9}, {%0,%1,%2,%3};"
                 : "+f"(c[0]), "+f"(c[1]), "+f"(c[2]), "+f"(c[3])
                 : "r"(a[0]), "r"(a[1]), "r"(a[2]), "r"(a[3]), "r"(b[0]), "r"(b[1]));
}
__device__ __forceinline__ uint32_t tile_addr(uint32_t base, int r, int u) {
    int up = u ^ ((r >> 1) & 3);
    return base + (uint32_t)(r * 4 + up) * 16u;
}
__device__ __forceinline__ void cp16(uint32_t daddr, const void* src, int sz) {
    asm volatile("cp.async.cg.shared.global [%0], [%1], 16, %2;"
                 :: "r"(daddr), "l"(src), "r"(sz) : "memory");
}

// ---------------------------------------------------------------------------
// dtype detect + zero scan base + zero deg
// ---------------------------------------------------------------------------
__global__ void detect_and_zero(const void* __restrict__ ei) {
    int i = blockIdx.x * blockDim.x + threadIdx.x;
    if (i < N_NODES) g_deg[i] = 0;
    if (blockIdx.x == 0 && threadIdx.x < 32) {
        int t = threadIdx.x;
        const long long* p = (const long long*)ei;
        int bad = 0;
        for (int k = t; k < 256; k += 32) {
            long long v = p[k];
            if (v < 0 || v >= N_NODES) bad = 1;
        }
        unsigned m = __ballot_sync(0xffffffffu, bad);
        if (t == 0) { g_idx_is64 = (m == 0u); g_total = 0; }
    }
}
__device__ __forceinline__ void load_edge(const void* ei, int e, int& src, int& dst) {
    if (g_idx_is64) {
        src = (int)((const long long*)ei)[e];
        dst = (int)((const long long*)ei)[E_EDGES + e];
    } else {
        src = ((const int*)ei)[e];
        dst = ((const int*)ei)[E_EDGES + e];
    }
}

// ---------------------------------------------------------------------------
// CSR build: hist -> one-pass scan -> bucket
// ---------------------------------------------------------------------------
__global__ void hist_dst(const void* __restrict__ ei) {
    int e = blockIdx.x * blockDim.x + threadIdx.x;
    if (e >= E_EDGES) return;
    int src, dst;
    load_edge(ei, e, src, dst);
    atomicAdd(&g_deg[dst], 1);
}
__global__ void scan_one() {
    __shared__ int s[256];
    __shared__ int sh_base;
    int b = blockIdx.x, t = threadIdx.x, i = b * 256 + t;
    int v = (i < N_NODES) ? g_deg[i] : 0;
    s[t] = v;
    __syncthreads();
    for (int o = 1; o < 256; o <<= 1) {
        int u = (t >= o) ? s[t - o] : 0;
        __syncthreads();
        s[t] += u;
        __syncthreads();
    }
    if (t == 255) sh_base = atomicAdd(&g_total, s[255]);
    __syncthreads();
    if (i < N_NODES) {
        int off = sh_base + s[t] - v;
        g_off[i] = off;
        g_cur[i] = off;
    }
}
__global__ void bucket_edges(const void* __restrict__ ei, const float* __restrict__ ew) {
    int e = blockIdx.x * blockDim.x + threadIdx.x;
    if (e >= E_EDGES) return;
    int src, dst;
    load_edge(ei, e, src, dst);
    int pos = atomicAdd(&g_cur[dst], 1);
    g_edge[pos] = make_uint2((unsigned)src, __float_as_uint(ew[e]));
}

// ---------------------------------------------------------------------------
// Fused prep: x0 -> fp16, weights -> transposed fp16 hi/lo split
// ---------------------------------------------------------------------------
#define PX0   (N_NODES * INC)
#define PW1   (INC * HID)
#define PW2   (HID * HID)
#define PLIN  (2 * HID * OUTC)
#define PWSUM (2 * PW1 + 2 * PW2 + PLIN)
#define PREP_TOTAL (PX0 + PWSUM)

__global__ void prep_all(const float* __restrict__ x0,
                         const float* __restrict__ wr1, const float* __restrict__ wo1,
                         const float* __restrict__ wr2, const float* __restrict__ wo2,
                         const float* __restrict__ lin) {
    long long i = (long long)blockIdx.x * blockDim.x + threadIdx.x;
    if (i >= PREP_TOTAL) return;
    if (i < PX0) {
        g_x0p[i] = __float2half(x0[i]);
        return;
    }
    long long j = i - PX0;
    const float* W; __half *th, *tl; int K, M; long long o;
    if (j < PW1)                { W = wr1; th = g_wr1h; tl = g_wr1l; K = INC; M = HID; o = j; }
    else if (j < 2 * PW1)       { W = wo1; th = g_wo1h; tl = g_wo1l; K = INC; M = HID; o = j - PW1; }
    else if (j < 2 * PW1 + PW2) { W = wr2; th = g_wr2h; tl = g_wr2l; K = HID; M = HID; o = j - 2 * PW1; }
    else if (j < 2 * PW1 + 2 * PW2) { W = wo2; th = g_wo2h; tl = g_wo2l; K = HID; M = HID; o = j - 2 * PW1 - PW2; }
    else                        { W = lin; th = g_linh; tl = g_linl; K = 2 * HID; M = OUTC; o = j - 2 * PW1 - 2 * PW2; }
    int k = (int)(o / M), m = (int)(o % M);
    float w = W[o];
    __half wh = __float2half(w);
    __half wl = __float2half(w - __half2float(wh));
    th[(size_t)m * K + k] = wh;
    tl[(size_t)m * K + k] = wl;
}

// ---------------------------------------------------------------------------
// CSR aggregation: warp per dst, 4 edges in flight, fp32 accum, fp16 store
// ---------------------------------------------------------------------------
__global__ __launch_bounds__(256)
void agg_csr_128(const __half* __restrict__ x, __half* __restrict__ o) {
    int d = blockIdx.x * 8 + (threadIdx.x >> 5);
    if (d >= N_NODES) return;
    int lane = threadIdx.x & 31;
    int beg = g_off[d], end = g_cur[d];
    float4 a0 = make_float4(0.f, 0.f, 0.f, 0.f);
    float4 a1 = make_float4(0.f, 0.f, 0.f, 0.f);
    int k = beg;
    for (; k + 3 < end; k += 4) {
        uint2 e0, e1, e2, e3;
        if ((k & 1) == 0) {
            uint4 q0 = *(const uint4*)&g_edge[k];
            uint4 q1 = *(const uint4*)&g_edge[k + 2];
            e0 = make_uint2(q0.x, q0.y); e1 = make_uint2(q0.z, q0.w);
            e2 = make_uint2(q1.x, q1.y); e3 = make_uint2(q1.z, q1.w);
        } else {
            e0 = g_edge[k]; e1 = g_edge[k + 1]; e2 = g_edge[k + 2]; e3 = g_edge[k + 3];
        }
        uint2 p0 = ((const uint2*)(x + (size_t)e0.x * INC))[lane];
        uint2 p1 = ((const uint2*)(x + (size_t)e1.x * INC))[lane];
        uint2 p2 = ((const uint2*)(x + (size_t)e2.x * INC))[lane];
        uint2 p3 = ((const uint2*)(x + (size_t)e3.x * INC))[lane];
        float w0 = __uint_as_float(e0.y), w1 = __uint_as_float(e1.y);
        float w2 = __uint_as_float(e2.y), w3 = __uint_as_float(e3.y);
        float2 f;
        f = __half22float2(*(const __half2*)&p0.x); a0.x = fmaf(w0, f.x, a0.x); a0.y = fmaf(w0, f.y, a0.y);
        f = __half22float2(*(const __half2*)&p0.y); a0.z = fmaf(w0, f.x, a0.z); a0.w = fmaf(w0, f.y, a0.w);
        f = __half22float2(*(const __half2*)&p1.x); a1.x = fmaf(w1, f.x, a1.x); a1.y = fmaf(w1, f.y, a1.y);
        f = __half22float2(*(const __half2*)&p1.y); a1.z = fmaf(w1, f.x, a1.z); a1.w = fmaf(w1, f.y, a1.w);
        f = __half22float2(*(const __half2*)&p2.x); a0.x = fmaf(w2, f.x, a0.x); a0.y = fmaf(w2, f.y, a0.y);
        f = __half22float2(*(const __half2*)&p2.y); a0.z = fmaf(w2, f.x, a0.z); a0.w = fmaf(w2, f.y, a0.w);
        f = __half22float2(*(const __half2*)&p3.x); a1.x = fmaf(w3, f.x, a1.x); a1.y = fmaf(w3, f.y, a1.y);
        f = __half22float2(*(const __half2*)&p3.y); a1.z = fmaf(w3, f.x, a1.z); a1.w = fmaf(w3, f.y, a1.w);
    }
    for (; k < end; ++k) {
        uint2 e0 = g_edge[k];
        float w0 = __uint_as_float(e0.y);
        uint2 p0 = ((const uint2*)(x + (size_t)e0.x * INC))[lane];
        float2 f;
        f = __half22float2(*(const __half2*)&p0.x); a0.x = fmaf(w0, f.x, a0.x); a0.y = fmaf(w0, f.y, a0.y);
        f = __half22float2(*(const __half2*)&p0.y); a0.z = fmaf(w0, f.x, a0.z); a0.w = fmaf(w0, f.y, a0.w);
    }
    a0.x += a1.x; a0.y += a1.y; a0.z += a1.z; a0.w += a1.w;
    uint2 st;
    st.x = h2_as_u32(__floats2half2_rn(a0.x, a0.y));
    st.y = h2_as_u32(__floats2half2_rn(a0.z, a0.w));
    *(uint2*)(o + (size_t)d * INC + lane * 4) = st;
}

__global__ __launch_bounds__(256)
void agg_csr_256(const __half* __restrict__ x, __half* __restrict__ o) {
    int d = blockIdx.x * 8 + (threadIdx.x >> 5);
    if (d >= N_NODES) return;
    int lane = threadIdx.x & 31;
    int beg = g_off[d], end = g_cur[d];
    float acc0[8], acc1[8];
#pragma unroll
    for (int j = 0; j < 8; ++j) { acc0[j] = 0.f; acc1[j] = 0.f; }
    int k = beg;
    for (; k + 3 < end; k += 4) {
        uint2 e0, e1, e2, e3;
        if ((k & 1) == 0) {
            uint4 q0 = *(const uint4*)&g_edge[k];
            uint4 q1 = *(const uint4*)&g_edge[k + 2];
            e0 = make_uint2(q0.x, q0.y); e1 = make_uint2(q0.z, q0.w);
            e2 = make_uint2(q1.x, q1.y); e3 = make_uint2(q1.z, q1.w);
        } else {
            e0 = g_edge[k]; e1 = g_edge[k + 1]; e2 = g_edge[k + 2]; e3 = g_edge[k + 3];
        }
        uint4 p0 = ((const uint4*)(x + (size_t)e0.x * HID))[lane];
        uint4 p1 = ((const uint4*)(x + (size_t)e1.x * HID))[lane];
        uint4 p2 = ((const uint4*)(x + (size_t)e2.x * HID))[lane];
        uint4 p3 = ((const uint4*)(x + (size_t)e3.x * HID))[lane];
        float w0 = __uint_as_float(e0.y), w1 = __uint_as_float(e1.y);
        float w2 = __uint_as_float(e2.y), w3 = __uint_as_float(e3.y);
        const __half2* h0 = (const __half2*)&p0;
        const __half2* h1 = (const __half2*)&p1;
        const __half2* h2 = (const __half2*)&p2;
        const __half2* h3 = (const __half2*)&p3;
#pragma unroll
        for (int j = 0; j < 4; ++j) {
            float2 f0 = __half22float2(h0[j]);
            float2 f1 = __half22float2(h1[j]);
            float2 f2 = __half22float2(h2[j]);
            float2 f3 = __half22float2(h3[j]);
            acc0[2 * j]     = fmaf(w0, f0.x, acc0[2 * j]);
            acc0[2 * j + 1] = fmaf(w0, f0.y, acc0[2 * j + 1]);
            acc1[2 * j]     = fmaf(w1, f1.x, acc1[2 * j]);
            acc1[2 * j + 1] = fmaf(w1, f1.y, acc1[2 * j + 1]);
            acc0[2 * j]     = fmaf(w2, f2.x, acc0[2 * j]);
            acc0[2 * j + 1] = fmaf(w2, f2.y, acc0[2 * j + 1]);
            acc1[2 * j]     = fmaf(w3, f3.x, acc1[2 * j]);
            acc1[2 * j + 1] = fmaf(w3, f3.y, acc1[2 * j + 1]);
        }
    }
    for (; k < end; ++k) {
        uint2 e0 = g_edge[k];
        float w0 = __uint_as_float(e0.y);
        uint4 p0 = ((const uint4*)(x + (size_t)e0.x * HID))[lane];
        const __half2* h0 = (const __half2*)&p0;
#pragma unroll
        for (int j = 0; j < 4; ++j) {
            float2 f0 = __half22float2(h0[j]);
            acc0[2 * j]     = fmaf(w0, f0.x, acc0[2 * j]);
            acc0[2 * j + 1] = fmaf(w0, f0.y, acc0[2 * j + 1]);
        }
    }
    uint4 st;
    st.x = h2_as_u32(__floats2half2_rn(acc0[0] + acc1[0], acc0[1] + acc1[1]));
    st.y = h2_as_u32(__floats2half2_rn(acc0[2] + acc1[2], acc0[3] + acc1[3]));
    st.z = h2_as_u32(__floats2half2_rn(acc0[4] + acc1[4], acc0[5] + acc1[5]));
    st.w = h2_as_u32(__floats2half2_rn(acc0[6] + acc1[6], acc0[7] + acc1[7]));
    *(uint4*)(o + (size_t)d * HID + lane * 8) = st;
}

// ---------------------------------------------------------------------------
// fp16 dual-source GEMM. WSPLIT=1: weights 2-term split (2 MMAs/tile);
// WSPLIT=0: plain fp16 weights (1 MMA/tile). cp.async 2-stage pipeline.
// ---------------------------------------------------------------------------
template <int BN, int WSPLIT>
__global__ __launch_bounds__(256, 2)
void gemm_h(const __half* __restrict__ A1, int K1,
            const __half* __restrict__ A2, int K2,
            const __half* __restrict__ B1h, const __half* __restrict__ B1l, int pb1,
            const __half* __restrict__ B2h, const __half* __restrict__ B2l, int pb2,
            const float* __restrict__ bias,
            float* __restrict__ outF, __half* __restrict__ outP,
            int Mout, int doRelu) {
    constexpr int NG = BN / 16;
    constexpr int NQ = BN / 32;
    constexpr int A_ELE = 128 * 32;                       // halves per A tile
    constexpr int B_ELE = BN * 32;                        // halves per B tile
    constexpr int NB = 1 + WSPLIT;                        // B tiles per stage
    constexpr int STG = A_ELE + NB * B_ELE;               // halves per stage

    extern __shared__ __align__(16) __half smh[];
    uint32_t base0 = smem_u32(smh);

    int tid = threadIdx.x, wid = tid >> 5, lane = tid & 31;
    int wm = (wid & 3) * 32;
    int wn = (wid >> 2) * (BN / 2);
    int row0 = blockIdx.x * 128;
    int col0 = blockIdx.y * BN;
    int rowsA = N_NODES - row0; if (rowsA > 128) rowsA = 128;
    int rowsB = Mout - col0;    if (rowsB > BN) rowsB = BN;

    const int nc1 = K1 / 32;
    const int NC = nc1 + K2 / 32;

    auto stage_chunk = [&](int c) {
        const __half *A, *Bh, *Bl;
        int pa, pb, kcol;
        if (c < nc1) { A = A1; pa = K1; Bh = B1h; Bl = B1l; pb = pb1; kcol = c * 32; }
        else         { A = A2; pa = K2; Bh = B2h; Bl = B2l; pb = pb2; kcol = (c - nc1) * 32; }
        A  += (size_t)row0 * pa;
        Bh += (size_t)col0 * pb;
        if (WSPLIT) Bl += (size_t)col0 * pb;
        uint32_t sb = base0 + (uint32_t)(c & 1) * STG * 2;
        for (int U = tid; U < 512; U += 256) {
            int r = U >> 2, u = U & 3;
            int up = u ^ ((r >> 1) & 3);
            int rs = (r < rowsA) ? r : 0;
            int sz = (r < rowsA) ? 16 : 0;
            cp16(sb + (uint32_t)(r * 4 + up) * 16u, A + (size_t)rs * pa + kcol + u * 8, sz);
        }
        uint32_t bb = sb + A_ELE * 2;
        for (int U = tid; U < BN * 4; U += 256) {
            int r = U >> 2, u = U & 3;
            int up = u ^ ((r >> 1) & 3);
            int rs = (r < rowsB) ? r : 0;
            int sz = (r < rowsB) ? 16 : 0;
            uint32_t da = bb + (uint32_t)(r * 4 + up) * 16u;
            cp16(da, Bh + (size_t)rs * pb + kcol + u * 8, sz);
            if (WSPLIT)
                cp16(da + B_ELE * 2, Bl + (size_t)rs * pb + kcol + u * 8, sz);
        }
    };

    float acc[2][NG][4];
#pragma unroll
    for (int i = 0; i < 2; ++i)
#pragma unroll
        for (int j = 0; j < NG; ++j)
#pragma unroll
            for (int q = 0; q < 4; ++q) acc[i][j][q] = 0.f;

    stage_chunk(0);
    asm volatile("cp.async.commit_group;" ::: "memory");

    for (int c = 0; c < NC; ++c) {
        if (c + 1 < NC) {
            stage_chunk(c + 1);
            asm volatile("cp.async.commit_group;" ::: "memory");
            asm volatile("cp.async.wait_group 1;" ::: "memory");
        } else {
            asm volatile("cp.async.wait_group 0;" ::: "memory");
        }
        __syncthreads();

        uint32_t sb  = base0 + (uint32_t)(c & 1) * STG * 2;
        uint32_t bA  = sb;
        uint32_t bBh = sb + A_ELE * 2;
        uint32_t bBl = bBh + B_ELE * 2;   // only valid when WSPLIT

#pragma unroll
        for (int ks = 0; ks < 2; ++ks) {
            int ksu = ks * 2;
            uint32_t fa[2][4];
#pragma unroll
            for (int mt = 0; mt < 2; ++mt) {
                int r = wm + mt * 16 + (lane & 15);
                int u = ksu + (lane >> 4);
                ldsm4(tile_addr(bA, r, u), fa[mt][0], fa[mt][1], fa[mt][2], fa[mt][3]);
            }
            uint32_t fbh[NQ][4], fbl[NQ][4];
#pragma unroll
            for (int q = 0; q < NQ; ++q) {
                int r = wn + q * 16 + (lane & 7) + ((lane & 16) ? 8 : 0);
                int u = ksu + ((lane >> 3) & 1);
                ldsm4(tile_addr(bBh, r, u), fbh[q][0], fbh[q][1], fbh[q][2], fbh[q][3]);
                if (WSPLIT)
                    ldsm4(tile_addr(bBl, r, u), fbl[q][0], fbl[q][1], fbl[q][2], fbl[q][3]);
            }
#pragma unroll
            for (int mt = 0; mt < 2; ++mt)
#pragma unroll
                for (int ng = 0; ng < NG; ++ng) {
                    const uint32_t* bpH = &fbh[ng >> 1][(ng & 1) * 2];
                    mma16816h(acc[mt][ng], fa[mt], bpH);
                    if (WSPLIT) {
                        const uint32_t* bpL = &fbl[ng >> 1][(ng & 1) * 2];
                        mma16816h(acc[mt][ng], fa[mt], bpL);
                    }
                }
        }
        __syncthreads();
    }

    // Epilogue
#pragma unroll
    for (int mt = 0; mt < 2; ++mt) {
        int rg = row0 + wm + mt * 16 + (lane >> 2);
#pragma unroll
        for (int half = 0; half < 2; ++half) {
            int r = rg + half * 8;
            if (r >= N_NODES) continue;
#pragma unroll
            for (int ng = 0; ng < NG; ++ng) {
                int c0 = col0 + wn + ng * 8 + (lane & 3) * 2;
#pragma unroll
                for (int q = 0; q < 2; ++q) {
                    int c = c0 + q;
                    if (c >= Mout) continue;
                    float v = acc[mt][ng][half * 2 + q] + bias[c];
                    if (doRelu) v = fmaxf(v, 0.f);
                    size_t idx = (size_t)r * Mout + c;
                    if (outF) outF[idx] = v;
                    if (outP) outP[idx] = __float2half(v);
                }
            }
        }
    }
}

// ---------------------------------------------------------------------------
extern "C" void kernel_launch(void* const* d_in, const int* in_sizes, int n_in,
                              void* d_out, int out_size) {
    const float* x0      = (const float*)d_in[0];
    const void*  ei      = d_in[1];
    const float* ew      = (const float*)d_in[2];
    const float* w_rel1  = (const float*)d_in[3];
    const float* b1      = (const float*)d_in[4];
    const float* w_root1 = (const float*)d_in[5];
    const float* w_rel2  = (const float*)d_in[6];
    const float* b2      = (const float*)d_in[7];
    const float* w_root2 = (const float*)d_in[8];
    const float* lin_w   = (const float*)d_in[9];
    const float* lin_b   = (const float*)d_in[10];
    float*       out     = (float*)d_out;

#define SYM(p, s) cudaGetSymbolAddress((void**)&p, s)
    __half *x0p, *a1p, *x1p, *a2p, *x2p;
    __half *wr1h, *wr1l, *wo1h, *wo1l, *wr2h, *wr2l, *wo2h, *wo2l, *linh, *linl;
    SYM(x0p, g_x0p); SYM(a1p, g_a1p); SYM(x1p, g_x1p);
    SYM(a2p, g_a2p); SYM(x2p, g_x2p);
    SYM(wr1h, g_wr1h); SYM(wr1l, g_wr1l); SYM(wo1h, g_wo1h); SYM(wo1l, g_wo1l);
    SYM(wr2h, g_wr2h); SYM(wr2l, g_wr2l); SYM(wo2h, g_wo2h); SYM(wo2l, g_wo2l);
    SYM(linh, g_linh); SYM(linl, g_linl);
#undef SYM

    // dynamic smem: 2 stages x (A + NB*B) fp16 tiles
    const int SM128_NS = 2 * (128 * 32 + 1 * 128 * 32) * 2;  // 32768 B (no split)
    const int SM64_S   = 2 * (128 * 32 + 2 * 64 * 32) * 2;   // 32768 B (split head)
    cudaFuncSetAttribute((const void*)gemm_h<128, 0>,
                         cudaFuncAttributeMaxDynamicSharedMemorySize, SM128_NS);
    cudaFuncSetAttribute((const void*)gemm_h<64, 1>,
                         cudaFuncAttributeMaxDynamicSharedMemorySize, SM64_S);

    const int eblk = (E_EDGES + 255) / 256;
    const int wblk = (N_NODES + 7) / 8;
    const int gblk = (N_NODES + 127) / 128;   // 391

    // 0) detect + deg zero, fused prep
    detect_and_zero<<<NB_SCAN, 256>>>(ei);
    prep_all<<<(PREP_TOTAL + 255) / 256, 256>>>(x0, w_rel1, w_root1, w_rel2, w_root2, lin_w);

    // 1) CSR build
    hist_dst<<<eblk, 256>>>(ei);
    scan_one<<<NB_SCAN, 256>>>();
    bucket_edges<<<eblk, 256>>>(ei, ew);

    // 2) layer 1 (plain fp16 weights, 1 MMA per tile)
    agg_csr_128<<<wblk, 256>>>(x0p, a1p);
    gemm_h<128, 0><<<dim3(gblk, 2), 256, SM128_NS>>>(a1p, INC, x0p, INC,
                                                     wr1h, (const __half*)0, INC,
                                                     wo1h, (const __half*)0, INC,
                                                     b1, (float*)0, x1p, HID, 1);
    // 3) layer 2 (plain fp16 weights)
    agg_csr_256<<<wblk, 256>>>(x1p, a2p);
    gemm_h<128, 0><<<dim3(gblk, 2), 256, SM128_NS>>>(a2p, HID, x1p, HID,
                                                     wr2h, (const __half*)0, HID,
                                                     wo2h, (const __half*)0, HID,
                                                     b2, (float*)0, x2p, HID, 1);
    // 4) head (keep 2-term weight split -- cheap, protects output accuracy)
    gemm_h<64, 1><<<dim3(gblk, 1), 256, SM64_S>>>(x1p, HID, x2p, HID,
                                                  linh, linl, 2 * HID,
                                                  linh + HID, linl + HID, 2 * HID,
                                                  lin_b, out, (__half*)0, OUTC, 0);
}

// round 16
// speedup vs baseline: 1.6942x; 1.0870x over previous
#include <cuda_runtime.h>
#include <cuda_fp16.h>
#include <stdint.h>

#define N_NODES 50000
#define E_EDGES 800000
#define INC 128
#define HID 256
#define OUTC 51
#define NB_SCAN 196   // ceil(50000/256)

// ---------------------------------------------------------------------------
// Scratch (static device globals -- allocation-free per harness rules)
// Activations fp16. Layer weights plain fp16 (hi only); head weights split.
// ---------------------------------------------------------------------------
__device__ __align__(16) __half g_x0p[N_NODES * INC];
__device__ __align__(16) __half g_a1p[N_NODES * INC];
__device__ __align__(16) __half g_x1p[N_NODES * HID];
__device__ __align__(16) __half g_a2p[N_NODES * HID];
__device__ __align__(16) __half g_x2p[N_NODES * HID];
__device__ __align__(16) __half g_wr1h[HID * INC],  g_wr1l[HID * INC];
__device__ __align__(16) __half g_wo1h[HID * INC],  g_wo1l[HID * INC];
__device__ __align__(16) __half g_wr2h[HID * HID],  g_wr2l[HID * HID];
__device__ __align__(16) __half g_wo2h[HID * HID],  g_wo2l[HID * HID];
__device__ __align__(16) __half g_linh[OUTC * 2 * HID], g_linl[OUTC * 2 * HID];
// CSR (payload packed: x = src, y = weight bits)
__device__ int   g_deg[N_NODES];
__device__ int   g_off[N_NODES];
__device__ int   g_cur[N_NODES];
__device__ __align__(16) uint2 g_edge[E_EDGES + 4];
__device__ int   g_total;
__device__ int   g_idx_is64;

// ---------------------------------------------------------------------------
// PTX helpers (baseline PTX only)
// ---------------------------------------------------------------------------
__device__ __forceinline__ uint32_t smem_u32(const void* p) {
    uint32_t a;
    asm("{ .reg .u64 t; cvta.to.shared.u64 t, %1; cvt.u32.u64 %0, t; }" : "=r"(a) : "l"(p));
    return a;
}
__device__ __forceinline__ uint32_t h2_as_u32(__half2 h) {
    uint32_t u;
    memcpy(&u, &h, 4);
    return u;
}
__device__ __forceinline__ void ldsm4(uint32_t addr, uint32_t& r0, uint32_t& r1,
                                      uint32_t& r2, uint32_t& r3) {
    asm volatile("ldmatrix.sync.aligned.m8n8.x4.shared.b16 {%0,%1,%2,%3}, [%4];"
                 : "=r"(r0), "=r"(r1), "=r"(r2), "=r"(r3) : "r"(addr));
}
__device__ __forceinline__ void mma16816h(float* c, const uint32_t* a, const uint32_t* b) {
    asm volatile("mma.sync.aligned.m16n8k16.row.col.f32.f16.f16.f32 "
                 "{%0,%1,%2,%3}, {%4,%5,%6,%7}, {%8,%9}, {%0,%1,%2,%3};"
                 : "+f"(c[0]), "+f"(c[1]), "+f"(c[2]), "+f"(c[3])
                 : "r"(a[0]), "r"(a[1]), "r"(a[2]), "r"(a[3]), "r"(b[0]), "r"(b[1]));
}
// SW128 swizzle for 128-byte rows (64 halves, 8 x 16B units per row)
__device__ __forceinline__ uint32_t tile_addr64(uint32_t base, int r, int u) {
    int up = u ^ (r & 7);
    return base + (uint32_t)(r * 8 + up) * 16u;
}
__device__ __forceinline__ void cp16(uint32_t daddr, const void* src, int sz) {
    asm volatile("cp.async.cg.shared.global [%0], [%1], 16, %2;"
                 :: "r"(daddr), "l"(src), "r"(sz) : "memory");
}

__device__ __forceinline__ void load_edge(const void* ei, int e, int& src, int& dst) {
    if (g_idx_is64) {
        src = (int)((const long long*)ei)[e];
        dst = (int)((const long long*)ei)[E_EDGES + e];
    } else {
        src = ((const int*)ei)[e];
        dst = ((const int*)ei)[E_EDGES + e];
    }
}

// ---------------------------------------------------------------------------
// Fused prep: dtype detect + deg zero + x0 -> fp16 + weight transpose-splits
// ---------------------------------------------------------------------------
#define PX0   (N_NODES * INC)
#define PW1   (INC * HID)
#define PW2   (HID * HID)
#define PLIN  (2 * HID * OUTC)
#define PWSUM (2 * PW1 + 2 * PW2 + PLIN)
#define PREP_TOTAL (PX0 + PWSUM + N_NODES)

__global__ void prep_all(const void* __restrict__ ei,
                         const float* __restrict__ x0,
                         const float* __restrict__ wr1, const float* __restrict__ wo1,
                         const float* __restrict__ wr2, const float* __restrict__ wo2,
                         const float* __restrict__ lin) {
    // dtype detect: block 0, warp 0 (int32 data read as int64 -> out of range)
    if (blockIdx.x == 0 && threadIdx.x < 32) {
        int t = threadIdx.x;
        const long long* p = (const long long*)ei;
        int bad = 0;
        for (int k = t; k < 256; k += 32) {
            long long v = p[k];
            if (v < 0 || v >= N_NODES) bad = 1;
        }
        unsigned m = __ballot_sync(0xffffffffu, bad);
        if (t == 0) { g_idx_is64 = (m == 0u); g_total = 0; }
    }
    long long i = (long long)blockIdx.x * blockDim.x + threadIdx.x;
    if (i >= PREP_TOTAL) return;
    if (i < PX0) {
        g_x0p[i] = __float2half(x0[i]);
        return;
    }
    long long j = i - PX0;
    if (j >= PWSUM) {                     // deg zero range
        g_deg[j - PWSUM] = 0;
        return;
    }
    const float* W; __half *th, *tl; int K, M; long long o;
    if (j < PW1)                { W = wr1; th = g_wr1h; tl = g_wr1l; K = INC; M = HID; o = j; }
    else if (j < 2 * PW1)       { W = wo1; th = g_wo1h; tl = g_wo1l; K = INC; M = HID; o = j - PW1; }
    else if (j < 2 * PW1 + PW2) { W = wr2; th = g_wr2h; tl = g_wr2l; K = HID; M = HID; o = j - 2 * PW1; }
    else if (j < 2 * PW1 + 2 * PW2) { W = wo2; th = g_wo2h; tl = g_wo2l; K = HID; M = HID; o = j - 2 * PW1 - PW2; }
    else                        { W = lin; th = g_linh; tl = g_linl; K = 2 * HID; M = OUTC; o = j - 2 * PW1 - 2 * PW2; }
    int k = (int)(o / M), m = (int)(o % M);
    float w = W[o];
    __half wh = __float2half(w);
    __half wl = __float2half(w - __half2float(wh));
    th[(size_t)m * K + k] = wh;
    tl[(size_t)m * K + k] = wl;
}

// ---------------------------------------------------------------------------
// CSR build: hist -> one-pass scan -> bucket
// ---------------------------------------------------------------------------
__global__ void hist_dst(const void* __restrict__ ei) {
    int e = blockIdx.x * blockDim.x + threadIdx.x;
    if (e >= E_EDGES) return;
    int src, dst;
    load_edge(ei, e, src, dst);
    atomicAdd(&g_deg[dst], 1);
}
__global__ void scan_one() {
    __shared__ int s[256];
    __shared__ int sh_base;
    int b = blockIdx.x, t = threadIdx.x, i = b * 256 + t;
    int v = (i < N_NODES) ? g_deg[i] : 0;
    s[t] = v;
    __syncthreads();
    for (int o = 1; o < 256; o <<= 1) {
        int u = (t >= o) ? s[t - o] : 0;
        __syncthreads();
        s[t] += u;
        __syncthreads();
    }
    if (t == 255) sh_base = atomicAdd(&g_total, s[255]);
    __syncthreads();
    if (i < N_NODES) {
        int off = sh_base + s[t] - v;
        g_off[i] = off;
        g_cur[i] = off;
    }
}
__global__ void bucket_edges(const void* __restrict__ ei, const float* __restrict__ ew) {
    int e = blockIdx.x * blockDim.x + threadIdx.x;
    if (e >= E_EDGES) return;
    int src, dst;
    load_edge(ei, e, src, dst);
    int pos = atomicAdd(&g_cur[dst], 1);
    g_edge[pos] = make_uint2((unsigned)src, __float_as_uint(ew[e]));
}

// ---------------------------------------------------------------------------
// CSR aggregation: warp per dst, 4 edges in flight, fp32 accum, fp16 store
// ---------------------------------------------------------------------------
__global__ __launch_bounds__(256)
void agg_csr_128(const __half* __restrict__ x, __half* __restrict__ o) {
    int d = blockIdx.x * 8 + (threadIdx.x >> 5);
    if (d >= N_NODES) return;
    int lane = threadIdx.x & 31;
    int beg = g_off[d], end = g_cur[d];
    float4 a0 = make_float4(0.f, 0.f, 0.f, 0.f);
    float4 a1 = make_float4(0.f, 0.f, 0.f, 0.f);
    int k = beg;
    for (; k + 3 < end; k += 4) {
        uint2 e0, e1, e2, e3;
        if ((k & 1) == 0) {
            uint4 q0 = *(const uint4*)&g_edge[k];
            uint4 q1 = *(const uint4*)&g_edge[k + 2];
            e0 = make_uint2(q0.x, q0.y); e1 = make_uint2(q0.z, q0.w);
            e2 = make_uint2(q1.x, q1.y); e3 = make_uint2(q1.z, q1.w);
        } else {
            e0 = g_edge[k]; e1 = g_edge[k + 1]; e2 = g_edge[k + 2]; e3 = g_edge[k + 3];
        }
        uint2 p0 = ((const uint2*)(x + (size_t)e0.x * INC))[lane];
        uint2 p1 = ((const uint2*)(x + (size_t)e1.x * INC))[lane];
        uint2 p2 = ((const uint2*)(x + (size_t)e2.x * INC))[lane];
        uint2 p3 = ((const uint2*)(x + (size_t)e3.x * INC))[lane];
        float w0 = __uint_as_float(e0.y), w1 = __uint_as_float(e1.y);
        float w2 = __uint_as_float(e2.y), w3 = __uint_as_float(e3.y);
        float2 f;
        f = __half22float2(*(const __half2*)&p0.x); a0.x = fmaf(w0, f.x, a0.x); a0.y = fmaf(w0, f.y, a0.y);
        f = __half22float2(*(const __half2*)&p0.y); a0.z = fmaf(w0, f.x, a0.z); a0.w = fmaf(w0, f.y, a0.w);
        f = __half22float2(*(const __half2*)&p1.x); a1.x = fmaf(w1, f.x, a1.x); a1.y = fmaf(w1, f.y, a1.y);
        f = __half22float2(*(const __half2*)&p1.y); a1.z = fmaf(w1, f.x, a1.z); a1.w = fmaf(w1, f.y, a1.w);
        f = __half22float2(*(const __half2*)&p2.x); a0.x = fmaf(w2, f.x, a0.x); a0.y = fmaf(w2, f.y, a0.y);
        f = __half22float2(*(const __half2*)&p2.y); a0.z = fmaf(w2, f.x, a0.z); a0.w = fmaf(w2, f.y, a0.w);
        f = __half22float2(*(const __half2*)&p3.x); a1.x = fmaf(w3, f.x, a1.x); a1.y = fmaf(w3, f.y, a1.y);
        f = __half22float2(*(const __half2*)&p3.y); a1.z = fmaf(w3, f.x, a1.z); a1.w = fmaf(w3, f.y, a1.w);
    }
    for (; k < end; ++k) {
        uint2 e0 = g_edge[k];
        float w0 = __uint_as_float(e0.y);
        uint2 p0 = ((const uint2*)(x + (size_t)e0.x * INC))[lane];
        float2 f;
        f = __half22float2(*(const __half2*)&p0.x); a0.x = fmaf(w0, f.x, a0.x); a0.y = fmaf(w0, f.y, a0.y);
        f = __half22float2(*(const __half2*)&p0.y); a0.z = fmaf(w0, f.x, a0.z); a0.w = fmaf(w0, f.y, a0.w);
    }
    a0.x += a1.x; a0.y += a1.y; a0.z += a1.z; a0.w += a1.w;
    uint2 st;
    st.x = h2_as_u32(__floats2half2_rn(a0.x, a0.y));
    st.y = h2_as_u32(__floats2half2_rn(a0.z, a0.w));
    *(uint2*)(o + (size_t)d * INC + lane * 4) = st;
}

__global__ __launch_bounds__(256)
void agg_csr_256(const __half* __restrict__ x, __half* __restrict__ o) {
    int d = blockIdx.x * 8 + (threadIdx.x >> 5);
    if (d >= N_NODES) return;
    int lane = threadIdx.x & 31;
    int beg = g_off[d], end = g_cur[d];
    float acc0[8], acc1[8];
#pragma unroll
    for (int j = 0; j < 8; ++j) { acc0[j] = 0.f; acc1[j] = 0.f; }
    int k = beg;
    for (; k + 3 < end; k += 4) {
        uint2 e0, e1, e2, e3;
        if ((k & 1) == 0) {
            uint4 q0 = *(const uint4*)&g_edge[k];
            uint4 q1 = *(const uint4*)&g_edge[k + 2];
            e0 = make_uint2(q0.x, q0.y); e1 = make_uint2(q0.z, q0.w);
            e2 = make_uint2(q1.x, q1.y); e3 = make_uint2(q1.z, q1.w);
        } else {
            e0 = g_edge[k]; e1 = g_edge[k + 1]; e2 = g_edge[k + 2]; e3 = g_edge[k + 3];
        }
        uint4 p0 = ((const uint4*)(x + (size_t)e0.x * HID))[lane];
        uint4 p1 = ((const uint4*)(x + (size_t)e1.x * HID))[lane];
        uint4 p2 = ((const uint4*)(x + (size_t)e2.x * HID))[lane];
        uint4 p3 = ((const uint4*)(x + (size_t)e3.x * HID))[lane];
        float w0 = __uint_as_float(e0.y), w1 = __uint_as_float(e1.y);
        float w2 = __uint_as_float(e2.y), w3 = __uint_as_float(e3.y);
        const __half2* h0 = (const __half2*)&p0;
        const __half2* h1 = (const __half2*)&p1;
        const __half2* h2 = (const __half2*)&p2;
        const __half2* h3 = (const __half2*)&p3;
#pragma unroll
        for (int j = 0; j < 4; ++j) {
            float2 f0 = __half22float2(h0[j]);
            float2 f1 = __half22float2(h1[j]);
            float2 f2 = __half22float2(h2[j]);
            float2 f3 = __half22float2(h3[j]);
            acc0[2 * j]     = fmaf(w0, f0.x, acc0[2 * j]);
            acc0[2 * j + 1] = fmaf(w0, f0.y, acc0[2 * j + 1]);
            acc1[2 * j]     = fmaf(w1, f1.x, acc1[2 * j]);
            acc1[2 * j + 1] = fmaf(w1, f1.y, acc1[2 * j + 1]);
            acc0[2 * j]     = fmaf(w2, f2.x, acc0[2 * j]);
            acc0[2 * j + 1] = fmaf(w2, f2.y, acc0[2 * j + 1]);
            acc1[2 * j]     = fmaf(w3, f3.x, acc1[2 * j]);
            acc1[2 * j + 1] = fmaf(w3, f3.y, acc1[2 * j + 1]);
        }
    }
    for (; k < end; ++k) {
        uint2 e0 = g_edge[k];
        float w0 = __uint_as_float(e0.y);
        uint4 p0 = ((const uint4*)(x + (size_t)e0.x * HID))[lane];
        const __half2* h0 = (const __half2*)&p0;
#pragma unroll
        for (int j = 0; j < 4; ++j) {
            float2 f0 = __half22float2(h0[j]);
            acc0[2 * j]     = fmaf(w0, f0.x, acc0[2 * j]);
            acc0[2 * j + 1] = fmaf(w0, f0.y, acc0[2 * j + 1]);
        }
    }
    uint4 st;
    st.x = h2_as_u32(__floats2half2_rn(acc0[0] + acc1[0], acc0[1] + acc1[1]));
    st.y = h2_as_u32(__floats2half2_rn(acc0[2] + acc1[2], acc0[3] + acc1[3]));
    st.z = h2_as_u32(__floats2half2_rn(acc0[4] + acc1[4], acc0[5] + acc1[5]));
    st.w = h2_as_u32(__floats2half2_rn(acc0[6] + acc1[6], acc0[7] + acc1[7]));
    *(uint4*)(o + (size_t)d * HID + lane * 8) = st;
}

// ---------------------------------------------------------------------------
// fp16 dual-source GEMM, 64-wide K chunks (halved barrier count vs 32).
// WSPLIT=1: weights 2-term split (2 MMAs/tile); WSPLIT=0: plain (1 MMA/tile).
// ---------------------------------------------------------------------------
template <int BN, int WSPLIT>
__global__ __launch_bounds__(256, 2)
void gemm_h(const __half* __restrict__ A1, int K1,
            const __half* __restrict__ A2, int K2,
            const __half* __restrict__ B1h, const __half* __restrict__ B1l, int pb1,
            const __half* __restrict__ B2h, const __half* __restrict__ B2l, int pb2,
            const float* __restrict__ bias,
            float* __restrict__ outF, __half* __restrict__ outP,
            int Mout, int doRelu) {
    constexpr int NG = BN / 16;
    constexpr int NQ = BN / 32;
    constexpr int KCH = 64;                               // halves per chunk
    constexpr int A_ELE = 128 * KCH;                      // halves per A tile
    constexpr int B_ELE = BN * KCH;                       // halves per B tile
    constexpr int NB = 1 + WSPLIT;
    constexpr int STG = A_ELE + NB * B_ELE;               // halves per stage

    extern __shared__ __align__(16) __half smh[];
    uint32_t base0 = smem_u32(smh);

    int tid = threadIdx.x, wid = tid >> 5, lane = tid & 31;
    int wm = (wid & 3) * 32;
    int wn = (wid >> 2) * (BN / 2);
    int row0 = blockIdx.x * 128;
    int col0 = blockIdx.y * BN;
    int rowsA = N_NODES - row0; if (rowsA > 128) rowsA = 128;
    int rowsB = Mout - col0;    if (rowsB > BN) rowsB = BN;

    const int nc1 = K1 / KCH;
    const int NC = nc1 + K2 / KCH;

    auto stage_chunk = [&](int c) {
        const __half *A, *Bh, *Bl;
        int pa, pb, kcol;
        if (c < nc1) { A = A1; pa = K1; Bh = B1h; Bl = B1l; pb = pb1; kcol = c * KCH; }
        else         { A = A2; pa = K2; Bh = B2h; Bl = B2l; pb = pb2; kcol = (c - nc1) * KCH; }
        A  += (size_t)row0 * pa;
        Bh += (size_t)col0 * pb;
        if (WSPLIT) Bl += (size_t)col0 * pb;
        uint32_t sb = base0 + (uint32_t)(c & 1) * STG * 2;
        // A: 128 rows x 8 units
        for (int U = tid; U < 128 * 8; U += 256) {
            int r = U >> 3, u = U & 7;
            int up = u ^ (r & 7);
            int rs = (r < rowsA) ? r : 0;
            int sz = (r < rowsA) ? 16 : 0;
            cp16(sb + (uint32_t)(r * 8 + up) * 16u, A + (size_t)rs * pa + kcol + u * 8, sz);
        }
        uint32_t bb = sb + A_ELE * 2;
        // B: BN rows x 8 units
        for (int U = tid; U < BN * 8; U += 256) {
            int r = U >> 3, u = U & 7;
            int up = u ^ (r & 7);
            int rs = (r < rowsB) ? r : 0;
            int sz = (r < rowsB) ? 16 : 0;
            uint32_t da = bb + (uint32_t)(r * 8 + up) * 16u;
            cp16(da, Bh + (size_t)rs * pb + kcol + u * 8, sz);
            if (WSPLIT)
                cp16(da + B_ELE * 2, Bl + (size_t)rs * pb + kcol + u * 8, sz);
        }
    };

    float acc[2][NG][4];
#pragma unroll
    for (int i = 0; i < 2; ++i)
#pragma unroll
        for (int j = 0; j < NG; ++j)
#pragma unroll
            for (int q = 0; q < 4; ++q) acc[i][j][q] = 0.f;

    stage_chunk(0);
    asm volatile("cp.async.commit_group;" ::: "memory");

    for (int c = 0; c < NC; ++c) {
        if (c + 1 < NC) {
            stage_chunk(c + 1);
            asm volatile("cp.async.commit_group;" ::: "memory");
            asm volatile("cp.async.wait_group 1;" ::: "memory");
        } else {
            asm volatile("cp.async.wait_group 0;" ::: "memory");
        }
        __syncthreads();

        uint32_t sb  = base0 + (uint32_t)(c & 1) * STG * 2;
        uint32_t bA  = sb;
        uint32_t bBh = sb + A_ELE * 2;
        uint32_t bBl = bBh + B_ELE * 2;   // valid when WSPLIT

#pragma unroll
        for (int ks = 0; ks < 4; ++ks) {   // 4 k-steps of 16 per 64-chunk
            int ksu = ks * 2;
            uint32_t fa[2][4];
#pragma unroll
            for (int mt = 0; mt < 2; ++mt) {
                int r = wm + mt * 16 + (lane & 15);
                int u = ksu + (lane >> 4);
                ldsm4(tile_addr64(bA, r, u), fa[mt][0], fa[mt][1], fa[mt][2], fa[mt][3]);
            }
            uint32_t fbh[NQ][4], fbl[NQ][4];
#pragma unroll
            for (int q = 0; q < NQ; ++q) {
                int r = wn + q * 16 + (lane & 7) + ((lane & 16) ? 8 : 0);
                int u = ksu + ((lane >> 3) & 1);
                ldsm4(tile_addr64(bBh, r, u), fbh[q][0], fbh[q][1], fbh[q][2], fbh[q][3]);
                if (WSPLIT)
                    ldsm4(tile_addr64(bBl, r, u), fbl[q][0], fbl[q][1], fbl[q][2], fbl[q][3]);
            }
#pragma unroll
            for (int mt = 0; mt < 2; ++mt)
#pragma unroll
                for (int ng = 0; ng < NG; ++ng) {
                    const uint32_t* bpH = &fbh[ng >> 1][(ng & 1) * 2];
                    mma16816h(acc[mt][ng], fa[mt], bpH);
                    if (WSPLIT) {
                        const uint32_t* bpL = &fbl[ng >> 1][(ng & 1) * 2];
                        mma16816h(acc[mt][ng], fa[mt], bpL);
                    }
                }
        }
        __syncthreads();
    }

    // Epilogue
#pragma unroll
    for (int mt = 0; mt < 2; ++mt) {
        int rg = row0 + wm + mt * 16 + (lane >> 2);
#pragma unroll
        for (int half = 0; half < 2; ++half) {
            int r = rg + half * 8;
            if (r >= N_NODES) continue;
#pragma unroll
            for (int ng = 0; ng < NG; ++ng) {
                int c0 = col0 + wn + ng * 8 + (lane & 3) * 2;
#pragma unroll
                for (int q = 0; q < 2; ++q) {
                    int c = c0 + q;
                    if (c >= Mout) continue;
                    float v = acc[mt][ng][half * 2 + q] + bias[c];
                    if (doRelu) v = fmaxf(v, 0.f);
                    size_t idx = (size_t)r * Mout + c;
                    if (outF) outF[idx] = v;
                    if (outP) outP[idx] = __float2half(v);
                }
            }
        }
    }
}

// ---------------------------------------------------------------------------
extern "C" void kernel_launch(void* const* d_in, const int* in_sizes, int n_in,
                              void* d_out, int out_size) {
    const float* x0      = (const float*)d_in[0];
    const void*  ei      = d_in[1];
    const float* ew      = (const float*)d_in[2];
    const float* w_rel1  = (const float*)d_in[3];
    const float* b1      = (const float*)d_in[4];
    const float* w_root1 = (const float*)d_in[5];
    const float* w_rel2  = (const float*)d_in[6];
    const float* b2      = (const float*)d_in[7];
    const float* w_root2 = (const float*)d_in[8];
    const float* lin_w   = (const float*)d_in[9];
    const float* lin_b   = (const float*)d_in[10];
    float*       out     = (float*)d_out;

#define SYM(p, s) cudaGetSymbolAddress((void**)&p, s)
    __half *x0p, *a1p, *x1p, *a2p, *x2p;
    __half *wr1h, *wr1l, *wo1h, *wo1l, *wr2h, *wr2l, *wo2h, *wo2l, *linh, *linl;
    SYM(x0p, g_x0p); SYM(a1p, g_a1p); SYM(x1p, g_x1p);
    SYM(a2p, g_a2p); SYM(x2p, g_x2p);
    SYM(wr1h, g_wr1h); SYM(wr1l, g_wr1l); SYM(wo1h, g_wo1h); SYM(wo1l, g_wo1l);
    SYM(wr2h, g_wr2h); SYM(wr2l, g_wr2l); SYM(wo2h, g_wo2h); SYM(wo2l, g_wo2l);
    SYM(linh, g_linh); SYM(linl, g_linl);
#undef SYM

    // dynamic smem: 2 stages x (A + NB*B) fp16 tiles, 64-wide K chunks
    const int SM128_NS = 2 * (128 * 64 + 1 * 128 * 64) * 2;  // 65536 B
    const int SM64_S   = 2 * (128 * 64 + 2 * 64 * 64) * 2;   // 65536 B
    cudaFuncSetAttribute((const void*)gemm_h<128, 0>,
                         cudaFuncAttributeMaxDynamicSharedMemorySize, SM128_NS);
    cudaFuncSetAttribute((const void*)gemm_h<64, 1>,
                         cudaFuncAttributeMaxDynamicSharedMemorySize, SM64_S);

    const int eblk = (E_EDGES + 255) / 256;
    const int wblk = (N_NODES + 7) / 8;
    const int gblk = (N_NODES + 127) / 128;   // 391

    // 0) fused prep (detect + deg zero + x0 fp16 + weight transposes)
    prep_all<<<(PREP_TOTAL + 255) / 256, 256>>>(ei, x0, w_rel1, w_root1,
                                                w_rel2, w_root2, lin_w);

    // 1) CSR build
    hist_dst<<<eblk, 256>>>(ei);
    scan_one<<<NB_SCAN, 256>>>();
    bucket_edges<<<eblk, 256>>>(ei, ew);

    // 2) layer 1
    agg_csr_128<<<wblk, 256>>>(x0p, a1p);
    gemm_h<128, 0><<<dim3(gblk, 2), 256, SM128_NS>>>(a1p, INC, x0p, INC,
                                                     wr1h, (const __half*)0, INC,
                                                     wo1h, (const __half*)0, INC,
                                                     b1, (float*)0, x1p, HID, 1);
    // 3) layer 2
    agg_csr_256<<<wblk, 256>>>(x1p, a2p);
    gemm_h<128, 0><<<dim3(gblk, 2), 256, SM128_NS>>>(a2p, HID, x1p, HID,
                                                     wr2h, (const __half*)0, HID,
                                                     wo2h, (const __half*)0, HID,
                                                     b2, (float*)0, x2p, HID, 1);
    // 4) head (2-term weight split retained)
    gemm_h<64, 1><<<dim3(gblk, 1), 256, SM64_S>>>(x1p, HID, x2p, HID,
                                                  linh, linl, 2 * HID,
                                                  linh + HID, linl + HID, 2 * HID,
                                                  lin_b, out, (__half*)0, OUTC, 0);
}

// round 17
// speedup vs baseline: 1.7050x; 1.0064x over previous
#include <cuda_runtime.h>
#include <cuda_fp16.h>
#include <stdint.h>

#define N_NODES 50000
#define E_EDGES 800000
#define E_HALF  400000
#define INC 128
#define HID 256
#define OUTC 51
#define NB_SCAN 196   // ceil(50000/256)

// ---------------------------------------------------------------------------
// Scratch (static device globals -- allocation-free per harness rules)
// Activations fp16; all weights plain fp16 (hi only; lo kept for fallback).
// ---------------------------------------------------------------------------
__device__ __align__(16) __half g_x0p[N_NODES * INC];
__device__ __align__(16) __half g_a1p[N_NODES * INC];
__device__ __align__(16) __half g_x1p[N_NODES * HID];
__device__ __align__(16) __half g_a2p[N_NODES * HID];
__device__ __align__(16) __half g_x2p[N_NODES * HID];
__device__ __align__(16) __half g_wr1h[HID * INC],  g_wr1l[HID * INC];
__device__ __align__(16) __half g_wo1h[HID * INC],  g_wo1l[HID * INC];
__device__ __align__(16) __half g_wr2h[HID * HID],  g_wr2l[HID * HID];
__device__ __align__(16) __half g_wo2h[HID * HID],  g_wo2l[HID * HID];
__device__ __align__(16) __half g_linh[OUTC * 2 * HID], g_linl[OUTC * 2 * HID];
// CSR (payload packed: x = src, y = weight bits)
__device__ int   g_deg[N_NODES];
__device__ int   g_off[N_NODES];
__device__ int   g_cur[N_NODES];
__device__ __align__(16) uint2 g_edge[E_EDGES + 4];
__device__ int   g_total;
__device__ int   g_idx_is64;

// ---------------------------------------------------------------------------
// PTX helpers (baseline PTX only)
// ---------------------------------------------------------------------------
__device__ __forceinline__ uint32_t smem_u32(const void* p) {
    uint32_t a;
    asm("{ .reg .u64 t; cvta.to.shared.u64 t, %1; cvt.u32.u64 %0, t; }" : "=r"(a) : "l"(p));
    return a;
}
__device__ __forceinline__ uint32_t h2_as_u32(__half2 h) {
    uint32_t u;
    memcpy(&u, &h, 4);
    return u;
}
__device__ __forceinline__ void ldsm4(uint32_t addr, uint32_t& r0, uint32_t& r1,
                                      uint32_t& r2, uint32_t& r3) {
    asm volatile("ldmatrix.sync.aligned.m8n8.x4.shared.b16 {%0,%1,%2,%3}, [%4];"
                 : "=r"(r0), "=r"(r1), "=r"(r2), "=r"(r3) : "r"(addr));
}
__device__ __forceinline__ void mma16816h(float* c, const uint32_t* a, const uint32_t* b) {
    asm volatile("mma.sync.aligned.m16n8k16.row.col.f32.f16.f16.f32 "
                 "{%0,%1,%2,%3}, {%4,%5,%6,%7}, {%8,%9}, {%0,%1,%2,%3};"
                 : "+f"(c[0]), "+f"(c[1]), "+f"(c[2]), "+f"(c[3])
                 : "r"(a[0]), "r"(a[1]), "r"(a[2]), "r"(a[3]), "r"(b[0]), "r"(b[1]));
}
// SW128 swizzle for 128-byte rows (64 halves, 8 x 16B units per row)
__device__ __forceinline__ uint32_t tile_addr64(uint32_t base, int r, int u) {
    int up = u ^ (r & 7);
    return base + (uint32_t)(r * 8 + up) * 16u;
}
__device__ __forceinline__ void cp16(uint32_t daddr, const void* src, int sz) {
    asm volatile("cp.async.cg.shared.global [%0], [%1], 16, %2;"
                 :: "r"(daddr), "l"(src), "r"(sz) : "memory");
}

__device__ __forceinline__ void load_edge(const void* ei, int e, int& src, int& dst) {
    if (g_idx_is64) {
        src = (int)((const long long*)ei)[e];
        dst = (int)((const long long*)ei)[E_EDGES + e];
    } else {
        src = ((const int*)ei)[e];
        dst = ((const int*)ei)[E_EDGES + e];
    }
}

// ---------------------------------------------------------------------------
// Fused prep: dtype detect + deg zero + x0 -> fp16 + weight transpose-splits
// ---------------------------------------------------------------------------
#define PX0   (N_NODES * INC)
#define PW1   (INC * HID)
#define PW2   (HID * HID)
#define PLIN  (2 * HID * OUTC)
#define PWSUM (2 * PW1 + 2 * PW2 + PLIN)
#define PREP_TOTAL (PX0 + PWSUM + N_NODES)

__global__ void prep_all(const void* __restrict__ ei,
                         const float* __restrict__ x0,
                         const float* __restrict__ wr1, const float* __restrict__ wo1,
                         const float* __restrict__ wr2, const float* __restrict__ wo2,
                         const float* __restrict__ lin) {
    if (blockIdx.x == 0 && threadIdx.x < 32) {
        int t = threadIdx.x;
        const long long* p = (const long long*)ei;
        int bad = 0;
        for (int k = t; k < 256; k += 32) {
            long long v = p[k];
            if (v < 0 || v >= N_NODES) bad = 1;
        }
        unsigned m = __ballot_sync(0xffffffffu, bad);
        if (t == 0) { g_idx_is64 = (m == 0u); g_total = 0; }
    }
    long long i = (long long)blockIdx.x * blockDim.x + threadIdx.x;
    if (i >= PREP_TOTAL) return;
    if (i < PX0) {
        g_x0p[i] = __float2half(x0[i]);
        return;
    }
    long long j = i - PX0;
    if (j >= PWSUM) {                     // deg zero range
        g_deg[j - PWSUM] = 0;
        return;
    }
    const float* W; __half *th, *tl; int K, M; long long o;
    if (j < PW1)                { W = wr1; th = g_wr1h; tl = g_wr1l; K = INC; M = HID; o = j; }
    else if (j < 2 * PW1)       { W = wo1; th = g_wo1h; tl = g_wo1l; K = INC; M = HID; o = j - PW1; }
    else if (j < 2 * PW1 + PW2) { W = wr2; th = g_wr2h; tl = g_wr2l; K = HID; M = HID; o = j - 2 * PW1; }
    else if (j < 2 * PW1 + 2 * PW2) { W = wo2; th = g_wo2h; tl = g_wo2l; K = HID; M = HID; o = j - 2 * PW1 - PW2; }
    else                        { W = lin; th = g_linh; tl = g_linl; K = 2 * HID; M = OUTC; o = j - 2 * PW1 - 2 * PW2; }
    int k = (int)(o / M), m = (int)(o % M);
    float w = W[o];
    __half wh = __float2half(w);
    __half wl = __float2half(w - __half2float(wh));
    th[(size_t)m * K + k] = wh;
    tl[(size_t)m * K + k] = wl;
}

// ---------------------------------------------------------------------------
// CSR build: hist -> one-pass scan -> bucket (2 edges/thread for MLP)
// ---------------------------------------------------------------------------
__global__ void hist_dst(const void* __restrict__ ei) {
    int e = blockIdx.x * blockDim.x + threadIdx.x;
    if (e >= E_HALF) return;
    int s0, d0, s1, d1;
    load_edge(ei, e, s0, d0);
    load_edge(ei, e + E_HALF, s1, d1);
    atomicAdd(&g_deg[d0], 1);
    atomicAdd(&g_deg[d1], 1);
}
__global__ void scan_one() {
    __shared__ int s[256];
    __shared__ int sh_base;
    int b = blockIdx.x, t = threadIdx.x, i = b * 256 + t;
    int v = (i < N_NODES) ? g_deg[i] : 0;
    s[t] = v;
    __syncthreads();
    for (int o = 1; o < 256; o <<= 1) {
        int u = (t >= o) ? s[t - o] : 0;
        __syncthreads();
        s[t] += u;
        __syncthreads();
    }
    if (t == 255) sh_base = atomicAdd(&g_total, s[255]);
    __syncthreads();
    if (i < N_NODES) {
        int off = sh_base + s[t] - v;
        g_off[i] = off;
        g_cur[i] = off;
    }
}
__global__ void bucket_edges(const void* __restrict__ ei, const float* __restrict__ ew) {
    int e = blockIdx.x * blockDim.x + threadIdx.x;
    if (e >= E_HALF) return;
    int s0, d0, s1, d1;
    load_edge(ei, e, s0, d0);
    load_edge(ei, e + E_HALF, s1, d1);
    float w0 = ew[e];
    float w1 = ew[e + E_HALF];
    int p0 = atomicAdd(&g_cur[d0], 1);
    int p1 = atomicAdd(&g_cur[d1], 1);
    g_edge[p0] = make_uint2((unsigned)s0, __float_as_uint(w0));
    g_edge[p1] = make_uint2((unsigned)s1, __float_as_uint(w1));
}

// ---------------------------------------------------------------------------
// CSR aggregation: warp per dst, 4 edges in flight, fp32 accum, fp16 store
// ---------------------------------------------------------------------------
__global__ __launch_bounds__(256)
void agg_csr_128(const __half* __restrict__ x, __half* __restrict__ o) {
    int d = blockIdx.x * 8 + (threadIdx.x >> 5);
    if (d >= N_NODES) return;
    int lane = threadIdx.x & 31;
    int beg = g_off[d], end = g_cur[d];
    float4 a0 = make_float4(0.f, 0.f, 0.f, 0.f);
    float4 a1 = make_float4(0.f, 0.f, 0.f, 0.f);
    int k = beg;
    for (; k + 3 < end; k += 4) {
        uint2 e0, e1, e2, e3;
        if ((k & 1) == 0) {
            uint4 q0 = *(const uint4*)&g_edge[k];
            uint4 q1 = *(const uint4*)&g_edge[k + 2];
            e0 = make_uint2(q0.x, q0.y); e1 = make_uint2(q0.z, q0.w);
            e2 = make_uint2(q1.x, q1.y); e3 = make_uint2(q1.z, q1.w);
        } else {
            e0 = g_edge[k]; e1 = g_edge[k + 1]; e2 = g_edge[k + 2]; e3 = g_edge[k + 3];
        }
        uint2 p0 = ((const uint2*)(x + (size_t)e0.x * INC))[lane];
        uint2 p1 = ((const uint2*)(x + (size_t)e1.x * INC))[lane];
        uint2 p2 = ((const uint2*)(x + (size_t)e2.x * INC))[lane];
        uint2 p3 = ((const uint2*)(x + (size_t)e3.x * INC))[lane];
        float w0 = __uint_as_float(e0.y), w1 = __uint_as_float(e1.y);
        float w2 = __uint_as_float(e2.y), w3 = __uint_as_float(e3.y);
        float2 f;
        f = __half22float2(*(const __half2*)&p0.x); a0.x = fmaf(w0, f.x, a0.x); a0.y = fmaf(w0, f.y, a0.y);
        f = __half22float2(*(const __half2*)&p0.y); a0.z = fmaf(w0, f.x, a0.z); a0.w = fmaf(w0, f.y, a0.w);
        f = __half22float2(*(const __half2*)&p1.x); a1.x = fmaf(w1, f.x, a1.x); a1.y = fmaf(w1, f.y, a1.y);
        f = __half22float2(*(const __half2*)&p1.y); a1.z = fmaf(w1, f.x, a1.z); a1.w = fmaf(w1, f.y, a1.w);
        f = __half22float2(*(const __half2*)&p2.x); a0.x = fmaf(w2, f.x, a0.x); a0.y = fmaf(w2, f.y, a0.y);
        f = __half22float2(*(const __half2*)&p2.y); a0.z = fmaf(w2, f.x, a0.z); a0.w = fmaf(w2, f.y, a0.w);
        f = __half22float2(*(const __half2*)&p3.x); a1.x = fmaf(w3, f.x, a1.x); a1.y = fmaf(w3, f.y, a1.y);
        f = __half22float2(*(const __half2*)&p3.y); a1.z = fmaf(w3, f.x, a1.z); a1.w = fmaf(w3, f.y, a1.w);
    }
    for (; k < end; ++k) {
        uint2 e0 = g_edge[k];
        float w0 = __uint_as_float(e0.y);
        uint2 p0 = ((const uint2*)(x + (size_t)e0.x * INC))[lane];
        float2 f;
        f = __half22float2(*(const __half2*)&p0.x); a0.x = fmaf(w0, f.x, a0.x); a0.y = fmaf(w0, f.y, a0.y);
        f = __half22float2(*(const __half2*)&p0.y); a0.z = fmaf(w0, f.x, a0.z); a0.w = fmaf(w0, f.y, a0.w);
    }
    a0.x += a1.x; a0.y += a1.y; a0.z += a1.z; a0.w += a1.w;
    uint2 st;
    st.x = h2_as_u32(__floats2half2_rn(a0.x, a0.y));
    st.y = h2_as_u32(__floats2half2_rn(a0.z, a0.w));
    *(uint2*)(o + (size_t)d * INC + lane * 4) = st;
}

__global__ __launch_bounds__(256)
void agg_csr_256(const __half* __restrict__ x, __half* __restrict__ o) {
    int d = blockIdx.x * 8 + (threadIdx.x >> 5);
    if (d >= N_NODES) return;
    int lane = threadIdx.x & 31;
    int beg = g_off[d], end = g_cur[d];
    float acc0[8], acc1[8];
#pragma unroll
    for (int j = 0; j < 8; ++j) { acc0[j] = 0.f; acc1[j] = 0.f; }
    int k = beg;
    for (; k + 3 < end; k += 4) {
        uint2 e0, e1, e2, e3;
        if ((k & 1) == 0) {
            uint4 q0 = *(const uint4*)&g_edge[k];
            uint4 q1 = *(const uint4*)&g_edge[k + 2];
            e0 = make_uint2(q0.x, q0.y); e1 = make_uint2(q0.z, q0.w);
            e2 = make_uint2(q1.x, q1.y); e3 = make_uint2(q1.z, q1.w);
        } else {
            e0 = g_edge[k]; e1 = g_edge[k + 1]; e2 = g_edge[k + 2]; e3 = g_edge[k + 3];
        }
        uint4 p0 = ((const uint4*)(x + (size_t)e0.x * HID))[lane];
        uint4 p1 = ((const uint4*)(x + (size_t)e1.x * HID))[lane];
        uint4 p2 = ((const uint4*)(x + (size_t)e2.x * HID))[lane];
        uint4 p3 = ((const uint4*)(x + (size_t)e3.x * HID))[lane];
        float w0 = __uint_as_float(e0.y), w1 = __uint_as_float(e1.y);
        float w2 = __uint_as_float(e2.y), w3 = __uint_as_float(e3.y);
        const __half2* h0 = (const __half2*)&p0;
        const __half2* h1 = (const __half2*)&p1;
        const __half2* h2 = (const __half2*)&p2;
        const __half2* h3 = (const __half2*)&p3;
#pragma unroll
        for (int j = 0; j < 4; ++j) {
            float2 f0 = __half22float2(h0[j]);
            float2 f1 = __half22float2(h1[j]);
            float2 f2 = __half22float2(h2[j]);
            float2 f3 = __half22float2(h3[j]);
            acc0[2 * j]     = fmaf(w0, f0.x, acc0[2 * j]);
            acc0[2 * j + 1] = fmaf(w0, f0.y, acc0[2 * j + 1]);
            acc1[2 * j]     = fmaf(w1, f1.x, acc1[2 * j]);
            acc1[2 * j + 1] = fmaf(w1, f1.y, acc1[2 * j + 1]);
            acc0[2 * j]     = fmaf(w2, f2.x, acc0[2 * j]);
            acc0[2 * j + 1] = fmaf(w2, f2.y, acc0[2 * j + 1]);
            acc1[2 * j]     = fmaf(w3, f3.x, acc1[2 * j]);
            acc1[2 * j + 1] = fmaf(w3, f3.y, acc1[2 * j + 1]);
        }
    }
    for (; k < end; ++k) {
        uint2 e0 = g_edge[k];
        float w0 = __uint_as_float(e0.y);
        uint4 p0 = ((const uint4*)(x + (size_t)e0.x * HID))[lane];
        const __half2* h0 = (const __half2*)&p0;
#pragma unroll
        for (int j = 0; j < 4; ++j) {
            float2 f0 = __half22float2(h0[j]);
            acc0[2 * j]     = fmaf(w0, f0.x, acc0[2 * j]);
            acc0[2 * j + 1] = fmaf(w0, f0.y, acc0[2 * j + 1]);
        }
    }
    uint4 st;
    st.x = h2_as_u32(__floats2half2_rn(acc0[0] + acc1[0], acc0[1] + acc1[1]));
    st.y = h2_as_u32(__floats2half2_rn(acc0[2] + acc1[2], acc0[3] + acc1[3]));
    st.z = h2_as_u32(__floats2half2_rn(acc0[4] + acc1[4], acc0[5] + acc1[5]));
    st.w = h2_as_u32(__floats2half2_rn(acc0[6] + acc1[6], acc0[7] + acc1[7]));
    *(uint4*)(o + (size_t)d * HID + lane * 8) = st;
}

// ---------------------------------------------------------------------------
// fp16 dual-source GEMM, 64-wide K chunks. WSPLIT as before.
// ---------------------------------------------------------------------------
template <int BN, int WSPLIT>
__global__ __launch_bounds__(256, 2)
void gemm_h(const __half* __restrict__ A1, int K1,
            const __half* __restrict__ A2, int K2,
            const __half* __restrict__ B1h, const __half* __restrict__ B1l, int pb1,
            const __half* __restrict__ B2h, const __half* __restrict__ B2l, int pb2,
            const float* __restrict__ bias,
            float* __restrict__ outF, __half* __restrict__ outP,
            int Mout, int doRelu) {
    constexpr int NG = BN / 16;
    constexpr int NQ = BN / 32;
    constexpr int KCH = 64;
    constexpr int A_ELE = 128 * KCH;
    constexpr int B_ELE = BN * KCH;
    constexpr int NB = 1 + WSPLIT;
    constexpr int STG = A_ELE + NB * B_ELE;

    extern __shared__ __align__(16) __half smh[];
    uint32_t base0 = smem_u32(smh);

    int tid = threadIdx.x, wid = tid >> 5, lane = tid & 31;
    int wm = (wid & 3) * 32;
    int wn = (wid >> 2) * (BN / 2);
    int row0 = blockIdx.x * 128;
    int col0 = blockIdx.y * BN;
    int rowsA = N_NODES - row0; if (rowsA > 128) rowsA = 128;
    int rowsB = Mout - col0;    if (rowsB > BN) rowsB = BN;

    const int nc1 = K1 / KCH;
    const int NC = nc1 + K2 / KCH;

    auto stage_chunk = [&](int c) {
        const __half *A, *Bh, *Bl;
        int pa, pb, kcol;
        if (c < nc1) { A = A1; pa = K1; Bh = B1h; Bl = B1l; pb = pb1; kcol = c * KCH; }
        else         { A = A2; pa = K2; Bh = B2h; Bl = B2l; pb = pb2; kcol = (c - nc1) * KCH; }
        A  += (size_t)row0 * pa;
        Bh += (size_t)col0 * pb;
        if (WSPLIT) Bl += (size_t)col0 * pb;
        uint32_t sb = base0 + (uint32_t)(c & 1) * STG * 2;
        for (int U = tid; U < 128 * 8; U += 256) {
            int r = U >> 3, u = U & 7;
            int up = u ^ (r & 7);
            int rs = (r < rowsA) ? r : 0;
            int sz = (r < rowsA) ? 16 : 0;
            cp16(sb + (uint32_t)(r * 8 + up) * 16u, A + (size_t)rs * pa + kcol + u * 8, sz);
        }
        uint32_t bb = sb + A_ELE * 2;
        for (int U = tid; U < BN * 8; U += 256) {
            int r = U >> 3, u = U & 7;
            int up = u ^ (r & 7);
            int rs = (r < rowsB) ? r : 0;
            int sz = (r < rowsB) ? 16 : 0;
            uint32_t da = bb + (uint32_t)(r * 8 + up) * 16u;
            cp16(da, Bh + (size_t)rs * pb + kcol + u * 8, sz);
            if (WSPLIT)
                cp16(da + B_ELE * 2, Bl + (size_t)rs * pb + kcol + u * 8, sz);
        }
    };

    float acc[2][NG][4];
#pragma unroll
    for (int i = 0; i < 2; ++i)
#pragma unroll
        for (int j = 0; j < NG; ++j)
#pragma unroll
            for (int q = 0; q < 4; ++q) acc[i][j][q] = 0.f;

    stage_chunk(0);
    asm volatile("cp.async.commit_group;" ::: "memory");

    for (int c = 0; c < NC; ++c) {
        if (c + 1 < NC) {
            stage_chunk(c + 1);
            asm volatile("cp.async.commit_group;" ::: "memory");
            asm volatile("cp.async.wait_group 1;" ::: "memory");
        } else {
            asm volatile("cp.async.wait_group 0;" ::: "memory");
        }
        __syncthreads();

        uint32_t sb  = base0 + (uint32_t)(c & 1) * STG * 2;
        uint32_t bA  = sb;
        uint32_t bBh = sb + A_ELE * 2;
        uint32_t bBl = bBh + B_ELE * 2;   // valid when WSPLIT

#pragma unroll
        for (int ks = 0; ks < 4; ++ks) {
            int ksu = ks * 2;
            uint32_t fa[2][4];
#pragma unroll
            for (int mt = 0; mt < 2; ++mt) {
                int r = wm + mt * 16 + (lane & 15);
                int u = ksu + (lane >> 4);
                ldsm4(tile_addr64(bA, r, u), fa[mt][0], fa[mt][1], fa[mt][2], fa[mt][3]);
            }
            uint32_t fbh[NQ][4], fbl[NQ][4];
#pragma unroll
            for (int q = 0; q < NQ; ++q) {
                int r = wn + q * 16 + (lane & 7) + ((lane & 16) ? 8 : 0);
                int u = ksu + ((lane >> 3) & 1);
                ldsm4(tile_addr64(bBh, r, u), fbh[q][0], fbh[q][1], fbh[q][2], fbh[q][3]);
                if (WSPLIT)
                    ldsm4(tile_addr64(bBl, r, u), fbl[q][0], fbl[q][1], fbl[q][2], fbl[q][3]);
            }
#pragma unroll
            for (int mt = 0; mt < 2; ++mt)
#pragma unroll
                for (int ng = 0; ng < NG; ++ng) {
                    const uint32_t* bpH = &fbh[ng >> 1][(ng & 1) * 2];
                    mma16816h(acc[mt][ng], fa[mt], bpH);
                    if (WSPLIT) {
                        const uint32_t* bpL = &fbl[ng >> 1][(ng & 1) * 2];
                        mma16816h(acc[mt][ng], fa[mt], bpL);
                    }
                }
        }
        __syncthreads();
    }

    // Epilogue
#pragma unroll
    for (int mt = 0; mt < 2; ++mt) {
        int rg = row0 + wm + mt * 16 + (lane >> 2);
#pragma unroll
        for (int half = 0; half < 2; ++half) {
            int r = rg + half * 8;
            if (r >= N_NODES) continue;
#pragma unroll
            for (int ng = 0; ng < NG; ++ng) {
                int c0 = col0 + wn + ng * 8 + (lane & 3) * 2;
#pragma unroll
                for (int q = 0; q < 2; ++q) {
                    int c = c0 + q;
                    if (c >= Mout) continue;
                    float v = acc[mt][ng][half * 2 + q] + bias[c];
                    if (doRelu) v = fmaxf(v, 0.f);
                    size_t idx = (size_t)r * Mout + c;
                    if (outF) outF[idx] = v;
                    if (outP) outP[idx] = __float2half(v);
                }
            }
        }
    }
}

// ---------------------------------------------------------------------------
extern "C" void kernel_launch(void* const* d_in, const int* in_sizes, int n_in,
                              void* d_out, int out_size) {
    const float* x0      = (const float*)d_in[0];
    const void*  ei      = d_in[1];
    const float* ew      = (const float*)d_in[2];
    const float* w_rel1  = (const float*)d_in[3];
    const float* b1      = (const float*)d_in[4];
    const float* w_root1 = (const float*)d_in[5];
    const float* w_rel2  = (const float*)d_in[6];
    const float* b2      = (const float*)d_in[7];
    const float* w_root2 = (const float*)d_in[8];
    const float* lin_w   = (const float*)d_in[9];
    const float* lin_b   = (const float*)d_in[10];
    float*       out     = (float*)d_out;

#define SYM(p, s) cudaGetSymbolAddress((void**)&p, s)
    __half *x0p, *a1p, *x1p, *a2p, *x2p;
    __half *wr1h, *wo1h, *wr2h, *wo2h, *linh;
    SYM(x0p, g_x0p); SYM(a1p, g_a1p); SYM(x1p, g_x1p);
    SYM(a2p, g_a2p); SYM(x2p, g_x2p);
    SYM(wr1h, g_wr1h); SYM(wo1h, g_wo1h);
    SYM(wr2h, g_wr2h); SYM(wo2h, g_wo2h);
    SYM(linh, g_linh);
#undef SYM

    // dynamic smem: 2 stages x (A + B) fp16 tiles, 64-wide K chunks
    const int SM128_NS = 2 * (128 * 64 + 128 * 64) * 2;  // 65536 B
    const int SM64_NS  = 2 * (128 * 64 + 64 * 64) * 2;   // 49152 B
    cudaFuncSetAttribute((const void*)gemm_h<128, 0>,
                         cudaFuncAttributeMaxDynamicSharedMemorySize, SM128_NS);
    cudaFuncSetAttribute((const void*)gemm_h<64, 0>,
                         cudaFuncAttributeMaxDynamicSharedMemorySize, SM64_NS);

    const int ehblk = (E_HALF + 255) / 256;   // 1563
    const int wblk  = (N_NODES + 7) / 8;
    const int gblk  = (N_NODES + 127) / 128;  // 391

    // 0) fused prep (detect + deg zero + x0 fp16 + weight transposes)
    prep_all<<<(PREP_TOTAL + 255) / 256, 256>>>(ei, x0, w_rel1, w_root1,
                                                w_rel2, w_root2, lin_w);

    // 1) CSR build (2 edges per thread)
    hist_dst<<<ehblk, 256>>>(ei);
    scan_one<<<NB_SCAN, 256>>>();
    bucket_edges<<<ehblk, 256>>>(ei, ew);

    // 2) layer 1
    agg_csr_128<<<wblk, 256>>>(x0p, a1p);
    gemm_h<128, 0><<<dim3(gblk, 2), 256, SM128_NS>>>(a1p, INC, x0p, INC,
                                                     wr1h, (const __half*)0, INC,
                                                     wo1h, (const __half*)0, INC,
                                                     b1, (float*)0, x1p, HID, 1);
    // 3) layer 2
    agg_csr_256<<<wblk, 256>>>(x1p, a2p);
    gemm_h<128, 0><<<dim3(gblk, 2), 256, SM128_NS>>>(a2p, HID, x1p, HID,
                                                     wr2h, (const __half*)0, HID,
                                                     wo2h, (const __half*)0, HID,
                                                     b2, (float*)0, x2p, HID, 1);
    // 4) head (plain fp16 weights now too)
    gemm_h<64, 0><<<dim3(gblk, 1), 256, SM64_NS>>>(x1p, HID, x2p, HID,
                                                   linh, (const __half*)0, 2 * HID,
                                                   linh + HID, (const __half*)0, 2 * HID,
                                                   lin_b, out, (__half*)0, OUTC, 0);
}